// round 10
// baseline (speedup 1.0000x reference)
#include <cuda_runtime.h>
#include <cuda_bf16.h>
#include <stdint.h>

// ---- problem constants ----
#define NTOK 2048
#define DDIM 512
#define GRP  8
#define NQH  8
#define AD1  128
#define AD2  64

// ---- scratch (device globals: allocation-free) ----
__device__ float g_Gp[8*DDIM*DDIM];      // split-K partials (reused for S1/S2)
__device__ float g_G[DDIM*DDIM];
__device__ float g_s[DDIM];
__device__ float g_u1[GRP*AD1];
__device__ float g_w1[GRP*AD1];
__device__ float g_S1[GRP*AD1*AD1];
__device__ float g_T1[GRP*DDIM*AD1];
__device__ float g_P1[GRP*DDIM*NQH*AD1];
__device__ float g_bP1[GRP*NQH*AD1];
__device__ float g_W1[GRP*DDIM*DDIM];
__device__ float g_b1[GRP*DDIM];
__device__ float g_o1[GRP*NTOK*DDIM];
__device__ float g_Wk2e[GRP*DDIM*AD2];
__device__ float g_Wv2e[GRP*DDIM*AD2];
__device__ float g_bk2e[GRP*AD2];
__device__ float g_bv2e[GRP*AD2];
__device__ float g_u2[GRP*AD2];
__device__ float g_w2[GRP*AD2];
__device__ float g_T2[GRP*DDIM*AD2];
__device__ float g_S2[GRP*AD2*AD2];
__device__ float g_bP2[GRP*NQH*AD2];
__device__ float g_P2[GRP*DDIM*NQH*AD2];
__device__ float g_b2[GRP*DDIM];
__device__ float g_W2[GRP*DDIM*DDIM];
__device__ float g_W23[GRP*DDIM*DDIM];
__device__ float g_b3[GRP*DDIM];

// ---- helpers ----
__device__ __forceinline__ uint32_t smem_u32(const void* p) {
    return (uint32_t)__cvta_generic_to_shared(p);
}
__device__ __forceinline__ uint32_t sw128(uint32_t off) {
    return off ^ ((off >> 3) & 0x70);
}
__device__ __forceinline__ uint32_t lds32(uint32_t a) {
    uint32_t v;
    asm volatile("ld.shared.b32 %0, [%1];" : "=r"(v) : "r"(a));
    return v;
}
__device__ __forceinline__ uint32_t lds32lo(uint32_t a) {  // lo plane at +16384
    uint32_t v;
    asm volatile("ld.shared.b32 %0, [%1+16384];" : "=r"(v) : "r"(a));
    return v;
}
__device__ __forceinline__ void sts64(uint32_t a, uint2 v) {
    asm volatile("st.shared.v2.b32 [%0], {%1,%2};"
                 :: "r"(a), "r"(v.x), "r"(v.y));
}
// split 4 fp32 into 4 bf16 hi + 4 bf16 lo (8B each)
__device__ __forceinline__ void split4(float4 f, uint2& hi, uint2& lo) {
    float a[4] = {f.x, f.y, f.z, f.w};
    unsigned h[4], l[4];
#pragma unroll
    for (int i = 0; i < 4; i++) {
        __nv_bfloat16 bh = __float2bfloat16(a[i]);
        float r = a[i] - __bfloat162float(bh);
        __nv_bfloat16 bl = __float2bfloat16(r);
        h[i] = (unsigned)__bfloat16_as_ushort(bh);
        l[i] = (unsigned)__bfloat16_as_ushort(bl);
    }
    hi = make_uint2(h[0] | (h[1] << 16), h[2] | (h[3] << 16));
    lo = make_uint2(l[0] | (l[1] << 16), l[2] | (l[3] << 16));
}
#define MMA16816(c, a0, a1, a2, a3, b0, b1) \
    asm volatile( \
        "mma.sync.aligned.m16n8k16.row.col.f32.bf16.bf16.f32 " \
        "{%0,%1,%2,%3}, {%4,%5,%6,%7}, {%8,%9}, {%0,%1,%2,%3};" \
        : "+f"((c)[0]), "+f"((c)[1]), "+f"((c)[2]), "+f"((c)[3]) \
        : "r"(a0), "r"(a1), "r"(a2), "r"(a3), "r"(b0), "r"(b1))

#define OFF_B 32768
#define OFF_STAGE 65536
#define STAGE_BYTES (64 * 132 * 4)
#define TG_SMEM (1024 + OFF_STAGE + STAGE_BYTES)   // ~100KB

// ============================================================================
// Batched tensor-core GEMM (bf16 hi/lo split, fp32 in/out), coalesced fills.
// C[128, ntile] per CTA = A[M,K] @ B[K,N] (+bias). 256 thr = 8 warps (2Mx4N).
// ============================================================================
__global__ __launch_bounds__(256)
void tgemm(const float* __restrict__ A, long long aO, long long aI,
           const float* __restrict__ B, const float* __restrict__ bias,
           float* __restrict__ C,
           const float* __restrict__ B2, const float* __restrict__ bias2,
           float* __restrict__ C2, int zsplit,
           long long bO, long long bI, long long biasO,
           long long cO, long long cI, int ldc,
           int N, int K, int ntile, int bshift)
{
    extern __shared__ char smraw[];
    uint32_t sb0 = smem_u32(smraw);
    uint32_t abase = (sb0 + 1023) & ~1023u;
    char* tiles = smraw + (abase - sb0);
    float* stage = (float*)(tiles + OFF_STAGE);

    int tid = threadIdx.x;
    int lane = tid & 31, w = tid >> 5;
    int gid = lane >> 2, tig = lane & 3;

    int z = blockIdx.z;
    const float* Bu = B; const float* biasu = bias; float* Cu = C;
    if (z >= zsplit) { z -= zsplit; Bu = B2; biasu = bias2; Cu = C2; }
    int bh = z >> bshift, bl = z & ((1 << bshift) - 1);
    const float* Ab = A + (long long)bh * aO + (long long)bl * aI;
    const float* Bb = Bu + (long long)bh * bO + (long long)bl * bI;
    float*       Cb = Cu + (long long)bh * cO + (long long)bl * cI;

    int m0 = blockIdx.y * 128;
    int n0b = blockIdx.x * ntile;

    int wm = w & 1, wn = w >> 1;
    int warp_m = wm * 64;
    int warp_n = wn * (ntile >> 2);
    int Ntiles = ntile >> 5;

    int SSTR = ntile + 4;
    int nf4B = (ntile == 128) ? 8 : 4;
    int bsh  = (ntile == 128) ? 5 : 4;
    int p2n, p2k0, p2cnt;
    if (ntile == 128) { p2n = (w & 3) * 32 + lane; p2k0 = (w >> 2) * 32; p2cnt = 32; }
    else              { p2n = (w & 1) * 32 + lane; p2k0 = (w >> 1) * 16; p2cnt = 16; }

    float acc[4][4][4];
#pragma unroll
    for (int i = 0; i < 4; i++)
#pragma unroll
        for (int j = 0; j < 4; j++)
#pragma unroll
            for (int k = 0; k < 4; k++) acc[i][j][k] = 0.f;

    uint32_t aB[4], bB[4];
#pragma unroll
    for (int mt = 0; mt < 4; mt++)
        aB[mt] = abase + (uint32_t)(warp_m + mt * 16 + gid) * 128;
#pragma unroll
    for (int nt = 0; nt < 4; nt++)
        bB[nt] = abase + OFF_B + (uint32_t)(warp_n + nt * 8 + gid) * 128;
    uint32_t rx = (uint32_t)gid << 4;

    int nchunk = K >> 6;
    for (int ch = 0; ch < nchunk; ch++) {
        int kc = ch << 6;
        if (ch) __syncthreads();

        // ---- A fill (coalesced) ----
#pragma unroll
        for (int i = 0; i < 8; i++) {
            int flat = tid + (i << 8);
            int row = flat >> 4;
            int c4 = (flat & 15) << 2;
            float4 f = *(const float4*)(Ab + (long long)(m0 + row) * K + kc + c4);
            uint2 hi, lo;
            split4(f, hi, lo);
            uint32_t sw = abase + sw128((uint32_t)row * 128 + c4 * 2);
            sts64(sw, hi);
            sts64(sw + 16384, lo);
        }
        // ---- B stage pass 1 (coalesced rows of B) ----
        for (int i = 0; i < nf4B; i++) {
            int flat = tid + (i << 8);
            int k = flat >> bsh;
            int c4 = (flat & ((1 << bsh) - 1)) << 2;
            float4 f = *(const float4*)(Bb + (long long)(kc + k) * N + n0b + c4);
            *(float4*)(stage + k * SSTR + c4) = f;
        }
        __syncthreads();
        // ---- B pass 2: stage columns -> swizzled bf16 hi/lo tiles ----
        for (int k = p2k0; k < p2k0 + p2cnt; k += 4) {
            float4 f = make_float4(stage[k * SSTR + p2n],
                                   stage[(k + 1) * SSTR + p2n],
                                   stage[(k + 2) * SSTR + p2n],
                                   stage[(k + 3) * SSTR + p2n]);
            uint2 hi, lo;
            split4(f, hi, lo);
            uint32_t sw = abase + OFF_B + sw128((uint32_t)p2n * 128 + k * 2);
            sts64(sw, hi);
            sts64(sw + 16384, lo);
        }
        __syncthreads();

        // ---- compute: 4 k16 steps ----
#pragma unroll
        for (int ks = 0; ks < 4; ks++) {
            uint32_t q0 = ((uint32_t)(ks * 32) + (uint32_t)tig * 4) ^ rx;
            uint32_t q1 = q0 ^ 16;
            uint32_t ah[4][4], al[4][4];
#pragma unroll
            for (int mt = 0; mt < 4; mt++) {
                uint32_t base = aB[mt];
                ah[mt][0] = lds32(base + q0);
                ah[mt][1] = lds32(base + 1024 + q0);
                ah[mt][2] = lds32(base + q1);
                ah[mt][3] = lds32(base + 1024 + q1);
                al[mt][0] = lds32lo(base + q0);
                al[mt][1] = lds32lo(base + 1024 + q0);
                al[mt][2] = lds32lo(base + q1);
                al[mt][3] = lds32lo(base + 1024 + q1);
            }
#pragma unroll
            for (int nt = 0; nt < 4; nt++) {
                if (nt >= Ntiles) break;
                uint32_t bb = bB[nt];
                uint32_t bh0 = lds32(bb + q0);
                uint32_t bh1 = lds32(bb + q1);
                uint32_t bl0 = lds32lo(bb + q0);
                uint32_t bl1 = lds32lo(bb + q1);
#pragma unroll
                for (int mt = 0; mt < 4; mt++) {
                    MMA16816(acc[mt][nt], ah[mt][0], ah[mt][1], ah[mt][2], ah[mt][3], bh0, bh1);
                    MMA16816(acc[mt][nt], ah[mt][0], ah[mt][1], ah[mt][2], ah[mt][3], bl0, bl1);
                    MMA16816(acc[mt][nt], al[mt][0], al[mt][1], al[mt][2], al[mt][3], bh0, bh1);
                }
            }
        }
    }

    const float* bp = biasu ? (biasu + (long long)bh * biasO + n0b) : (const float*)nullptr;
#pragma unroll
    for (int mt = 0; mt < 4; mt++) {
        long long r0 = m0 + warp_m + mt * 16 + gid;
#pragma unroll
        for (int nt = 0; nt < 4; nt++) {
            if (nt >= Ntiles) break;
            int cc = warp_n + nt * 8 + 2 * tig;
            float b0 = 0.f, b1 = 0.f;
            if (bp) { b0 = bp[cc]; b1 = bp[cc + 1]; }
            float2 v0 = make_float2(acc[mt][nt][0] + b0, acc[mt][nt][1] + b1);
            float2 v1 = make_float2(acc[mt][nt][2] + b0, acc[mt][nt][3] + b1);
            *(float2*)&Cb[r0 * ldc + n0b + cc]       = v0;
            *(float2*)&Cb[(r0 + 8) * ldc + n0b + cc] = v1;
        }
    }
}

// ============================================================================
// TN tensor-core GEMM, split-K x8 partials: Cp[z] = A_slice^T @ B_slice.
// A is [Ktot, M] row-major per batch, B is [Ktot, N]. Tile 128x128.
// ============================================================================
__global__ __launch_bounds__(256)
void tgemm_tn(const float* __restrict__ A, long long aO,
              const float* __restrict__ B, long long bO,
              float* __restrict__ Cp, int M, int N, int Ktot)
{
    extern __shared__ char smraw[];
    uint32_t sb0 = smem_u32(smraw);
    uint32_t abase = (sb0 + 1023) & ~1023u;
    char* tiles = smraw + (abase - sb0);
    float* stage = (float*)(tiles + OFF_STAGE);

    int tid = threadIdx.x;
    int lane = tid & 31, w = tid >> 5;
    int gid = lane >> 2, tig = lane & 3;

    int z = blockIdx.z;
    int g = z >> 3, c = z & 7;
    int kl = Ktot >> 3;
    const float* Ab = A + (long long)g * aO + (long long)c * kl * M;
    const float* Bb = B + (long long)g * bO + (long long)c * kl * N;
    float*       Cb = Cp + (long long)z * M * N;

    int m0 = blockIdx.y * 128;
    int n0b = blockIdx.x * 128;

    int wm = w & 1, wn = w >> 1;
    int warp_m = wm * 64;
    int warp_n = wn * 32;

    int p2n = (w & 3) * 32 + lane;
    int p2k0 = (w >> 2) * 32;

    float acc[4][4][4];
#pragma unroll
    for (int i = 0; i < 4; i++)
#pragma unroll
        for (int j = 0; j < 4; j++)
#pragma unroll
            for (int k = 0; k < 4; k++) acc[i][j][k] = 0.f;

    uint32_t aB[4], bB[4];
#pragma unroll
    for (int mt = 0; mt < 4; mt++)
        aB[mt] = abase + (uint32_t)(warp_m + mt * 16 + gid) * 128;
#pragma unroll
    for (int nt = 0; nt < 4; nt++)
        bB[nt] = abase + OFF_B + (uint32_t)(warp_n + nt * 8 + gid) * 128;
    uint32_t rx = (uint32_t)gid << 4;

    int nchunk = kl >> 6;
    for (int ch = 0; ch < nchunk; ch++) {
        int kc = ch << 6;
        if (ch) __syncthreads();

        // ---- A stage pass 1: 64 k-rows x 128 m, coalesced ----
#pragma unroll
        for (int i = 0; i < 8; i++) {
            int flat = tid + (i << 8);
            int k = flat >> 5;
            int c4 = (flat & 31) << 2;
            float4 f = *(const float4*)(Ab + (long long)(kc + k) * M + m0 + c4);
            *(float4*)(stage + k * 132 + c4) = f;
        }
        __syncthreads();
        // ---- A pass 2: stage columns -> swizzled bf16 tiles (m-major) ----
        for (int k = p2k0; k < p2k0 + 32; k += 4) {
            float4 f = make_float4(stage[k * 132 + p2n],
                                   stage[(k + 1) * 132 + p2n],
                                   stage[(k + 2) * 132 + p2n],
                                   stage[(k + 3) * 132 + p2n]);
            uint2 hi, lo;
            split4(f, hi, lo);
            uint32_t sw = abase + sw128((uint32_t)p2n * 128 + k * 2);
            sts64(sw, hi);
            sts64(sw + 16384, lo);
        }
        __syncthreads();
        // ---- B stage pass 1 ----
#pragma unroll
        for (int i = 0; i < 8; i++) {
            int flat = tid + (i << 8);
            int k = flat >> 5;
            int c4 = (flat & 31) << 2;
            float4 f = *(const float4*)(Bb + (long long)(kc + k) * N + n0b + c4);
            *(float4*)(stage + k * 132 + c4) = f;
        }
        __syncthreads();
        // ---- B pass 2 ----
        for (int k = p2k0; k < p2k0 + 32; k += 4) {
            float4 f = make_float4(stage[k * 132 + p2n],
                                   stage[(k + 1) * 132 + p2n],
                                   stage[(k + 2) * 132 + p2n],
                                   stage[(k + 3) * 132 + p2n]);
            uint2 hi, lo;
            split4(f, hi, lo);
            uint32_t sw = abase + OFF_B + sw128((uint32_t)p2n * 128 + k * 2);
            sts64(sw, hi);
            sts64(sw + 16384, lo);
        }
        __syncthreads();

        // ---- compute (identical to tgemm, Ntiles=4) ----
#pragma unroll
        for (int ks = 0; ks < 4; ks++) {
            uint32_t q0 = ((uint32_t)(ks * 32) + (uint32_t)tig * 4) ^ rx;
            uint32_t q1 = q0 ^ 16;
            uint32_t ah[4][4], al[4][4];
#pragma unroll
            for (int mt = 0; mt < 4; mt++) {
                uint32_t base = aB[mt];
                ah[mt][0] = lds32(base + q0);
                ah[mt][1] = lds32(base + 1024 + q0);
                ah[mt][2] = lds32(base + q1);
                ah[mt][3] = lds32(base + 1024 + q1);
                al[mt][0] = lds32lo(base + q0);
                al[mt][1] = lds32lo(base + 1024 + q0);
                al[mt][2] = lds32lo(base + q1);
                al[mt][3] = lds32lo(base + 1024 + q1);
            }
#pragma unroll
            for (int nt = 0; nt < 4; nt++) {
                uint32_t bb = bB[nt];
                uint32_t bh0 = lds32(bb + q0);
                uint32_t bh1 = lds32(bb + q1);
                uint32_t bl0 = lds32lo(bb + q0);
                uint32_t bl1 = lds32lo(bb + q1);
#pragma unroll
                for (int mt = 0; mt < 4; mt++) {
                    MMA16816(acc[mt][nt], ah[mt][0], ah[mt][1], ah[mt][2], ah[mt][3], bh0, bh1);
                    MMA16816(acc[mt][nt], ah[mt][0], ah[mt][1], ah[mt][2], ah[mt][3], bl0, bl1);
                    MMA16816(acc[mt][nt], al[mt][0], al[mt][1], al[mt][2], al[mt][3], bh0, bh1);
                }
            }
        }
    }

#pragma unroll
    for (int mt = 0; mt < 4; mt++) {
        long long r0 = m0 + warp_m + mt * 16 + gid;
#pragma unroll
        for (int nt = 0; nt < 4; nt++) {
            int cc = warp_n + nt * 8 + 2 * tig;
            float2 v0 = make_float2(acc[mt][nt][0], acc[mt][nt][1]);
            float2 v1 = make_float2(acc[mt][nt][2], acc[mt][nt][3]);
            *(float2*)&Cb[r0 * N + n0b + cc]       = v0;
            *(float2*)&Cb[(r0 + 8) * N + n0b + cc] = v1;
        }
    }
}

// ============================================================================
// Split-K TN GEMM partials (fp32): Cp[z] = A_slice^T @ B_slice
// ============================================================================
__global__ __launch_bounds__(256)
void gemm_tn_sk(const float* __restrict__ A, long long aO,
                const float* __restrict__ B, long long bO,
                float* __restrict__ Cp, int M, int N, int Ktot)
{
    int z = blockIdx.z;
    int g = z >> 3, c = z & 7;
    int kl = Ktot >> 3;
    const float* Ab = A + (long long)g * aO + (long long)c * kl * M;
    const float* Bb = B + (long long)g * bO + (long long)c * kl * N;
    float*       Cb = Cp + (long long)z * M * N;

    __shared__ __align__(16) float As[16][64];
    __shared__ __align__(16) float Bs[16][64];

    int tid = threadIdx.x;
    int m0 = blockIdx.y * 64;
    int n0 = blockIdx.x * 64;

    int lrow = tid >> 4;
    int lcol = (tid & 15) * 4;
    int tx = tid & 15;
    int ty = tid >> 4;

    const float* Ap = Ab + (long long)lrow * M + m0 + lcol;
    const float* Bp = Bb + (long long)lrow * N + n0 + lcol;

    float acc[4][4];
#pragma unroll
    for (int i = 0; i < 4; i++)
#pragma unroll
        for (int j = 0; j < 4; j++) acc[i][j] = 0.f;

    for (int k0 = 0; k0 < kl; k0 += 16) {
        *(float4*)&As[lrow][lcol] = *(const float4*)(Ap + (long long)k0 * M);
        *(float4*)&Bs[lrow][lcol] = *(const float4*)(Bp + (long long)k0 * N);
        __syncthreads();
#pragma unroll
        for (int kk = 0; kk < 16; kk++) {
            float4 a = *(const float4*)&As[kk][ty * 4];
            float4 bb4 = *(const float4*)&Bs[kk][tx * 4];
            float a4[4] = {a.x, a.y, a.z, a.w};
            float b4[4] = {bb4.x, bb4.y, bb4.z, bb4.w};
#pragma unroll
            for (int i = 0; i < 4; i++)
#pragma unroll
                for (int j = 0; j < 4; j++)
                    acc[i][j] = fmaf(a4[i], b4[j], acc[i][j]);
        }
        __syncthreads();
    }

#pragma unroll
    for (int i = 0; i < 4; i++) {
        int row = m0 + ty * 4 + i;
        float4 v = {acc[i][0], acc[i][1], acc[i][2], acc[i][3]};
        *(float4*)&Cb[(long long)row * N + n0 + tx * 4] = v;
    }
}

// C[g] = alpha * sum_c Cp[g*8+c]
__global__ void reduce8(const float* __restrict__ Cp, float* __restrict__ C,
                        float alpha, int MN)
{
    int i = blockIdx.x * 256 + threadIdx.x;
    int g = blockIdx.y;
    const float* p = Cp + (long long)g * 8 * MN + i;
    float s = 0.f;
#pragma unroll
    for (int c = 0; c < 8; c++) s += p[(long long)c * MN];
    C[(long long)g * MN + i] = alpha * s;
}

// S[g][i][j] = alpha*(sum_c Cp + u[g][i]*bv[g][j] + bk[g][i]*w[g][j] + NTOK*bk[g][i]*bv[g][j])
__global__ void reduceS(const float* __restrict__ Cp, float* __restrict__ S,
                        const float* __restrict__ u, const float* __restrict__ bk,
                        const float* __restrict__ w, const float* __restrict__ bv,
                        float alpha, int MN, int M, int N)
{
    int i = blockIdx.x * 256 + threadIdx.x;
    int g = blockIdx.y;
    const float* p = Cp + (long long)g * 8 * MN + i;
    float ssum = 0.f;
#pragma unroll
    for (int c = 0; c < 8; c++) ssum += p[(long long)c * MN];
    int row = i / N, col = i - row * N;
    float uk = u[g * M + row], bki = bk[g * M + row];
    float wv = w[g * N + col], bvj = bv[g * N + col];
    ssum += uk * bvj + bki * wv + (float)NTOK * bki * bvj;
    S[(long long)g * MN + i] = alpha * ssum;
}

// s[c] = sum_n x[n][c]
__global__ void colsum(const float* __restrict__ x, float* __restrict__ s)
{
    int c = blockIdx.x * 256 + threadIdx.x;
    float a0 = 0.f, a1 = 0.f, a2 = 0.f, a3 = 0.f;
    const float* p = x + c;
    for (int n = 0; n < NTOK; n += 4) {
        a0 += p[(long long)n * DDIM];
        a1 += p[(long long)(n + 1) * DDIM];
        a2 += p[(long long)(n + 2) * DDIM];
        a3 += p[(long long)(n + 3) * DDIM];
    }
    s[c] = (a0 + a1) + (a2 + a3);
}

// ============================================================================
// Batched vec @ mat: 8-way K-split x 32 cols per block.
// ============================================================================
__global__ __launch_bounds__(256)
void vecmat3(const float* __restrict__ vec, long long vecStride,
             const float* __restrict__ mat, long long matO, long long matI, int bshift,
             const float* __restrict__ add, long long addStride,
             float* __restrict__ out, long long outStride,
             const float* __restrict__ vec2, const float* __restrict__ mat2,
             const float* __restrict__ add2, float* __restrict__ out2,
             int ysplit, int K, int N)
{
    int b = blockIdx.y;
    const float* vecu = vec; const float* matu = mat;
    const float* addu = add; float* outu = out;
    if (b >= ysplit) { b -= ysplit; vecu = vec2; matu = mat2; addu = add2; outu = out2; }
    int c = (threadIdx.x & 31) + blockIdx.x * 32;
    int s = threadIdx.x >> 5;
    const float* v = vecu + (long long)b * vecStride;
    const float* m = matu + (long long)(b >> bshift) * matO
                          + (long long)(b & ((1 << bshift) - 1)) * matI;
    int kpart = K >> 3;
    int kb = s * kpart;
    float a0 = 0.f, a1 = 0.f, a2 = 0.f, a3 = 0.f;
    if (c < N) {
        const float* mp = m + (long long)kb * N + c;
        const float* vp = v + kb;
        for (int k = 0; k < kpart; k += 4) {
            a0 = fmaf(vp[k],     mp[(long long)k * N], a0);
            a1 = fmaf(vp[k + 1], mp[(long long)(k + 1) * N], a1);
            a2 = fmaf(vp[k + 2], mp[(long long)(k + 2) * N], a2);
            a3 = fmaf(vp[k + 3], mp[(long long)(k + 3) * N], a3);
        }
    }
    __shared__ float red[256];
    red[threadIdx.x] = (a0 + a1) + (a2 + a3);
    __syncthreads();
    if (s == 0 && c < N) {
        float t = 0.f;
#pragma unroll
        for (int i = 0; i < 8; i++) t += red[threadIdx.x + i * 32];
        if (addu) t += addu[(long long)b * addStride + c];
        outu[(long long)b * outStride + c] = t;
    }
}

#define NOSET2 (const float*)nullptr, (const float*)nullptr, (float*)nullptr, (1<<30)
#define NOVEC2 nullptr, nullptr, nullptr, nullptr, (1<<30)

extern "C" void kernel_launch(void* const* d_in, const int* in_sizes, int n_in,
                              void* d_out, int out_size)
{
    (void)in_sizes; (void)n_in; (void)out_size;

    const float* x   = (const float*)d_in[0];
    const float* Wq1 = (const float*)d_in[1];
    const float* bq1 = (const float*)d_in[2];
    const float* Wk1 = (const float*)d_in[3];
    const float* bk1 = (const float*)d_in[4];
    const float* Wv1 = (const float*)d_in[5];
    const float* bv1 = (const float*)d_in[6];
    const float* Wo1 = (const float*)d_in[7];
    const float* bo1 = (const float*)d_in[8];
    const float* Wq2 = (const float*)d_in[9];
    const float* bq2 = (const float*)d_in[10];
    const float* Wk2 = (const float*)d_in[11];
    const float* bk2 = (const float*)d_in[12];
    const float* Wv2 = (const float*)d_in[13];
    const float* bv2 = (const float*)d_in[14];
    const float* Wo2 = (const float*)d_in[15];
    const float* bo2 = (const float*)d_in[16];
    const float* Wo  = (const float*)d_in[17];
    const float* bo  = (const float*)d_in[18];
    float* out = (float*)d_out;

    float *Gp, *G, *s, *u1, *w1, *S1, *T1, *P1, *bP1, *W1, *b1, *o1;
    float *Wk2e, *Wv2e, *bk2e, *bv2e, *u2, *w2, *T2, *S2, *bP2, *P2, *b2;
    float *W2, *W23, *b3;
    cudaGetSymbolAddress((void**)&Gp,   g_Gp);
    cudaGetSymbolAddress((void**)&G,    g_G);
    cudaGetSymbolAddress((void**)&s,    g_s);
    cudaGetSymbolAddress((void**)&u1,   g_u1);
    cudaGetSymbolAddress((void**)&w1,   g_w1);
    cudaGetSymbolAddress((void**)&S1,   g_S1);
    cudaGetSymbolAddress((void**)&T1,   g_T1);
    cudaGetSymbolAddress((void**)&P1,   g_P1);
    cudaGetSymbolAddress((void**)&bP1,  g_bP1);
    cudaGetSymbolAddress((void**)&W1,   g_W1);
    cudaGetSymbolAddress((void**)&b1,   g_b1);
    cudaGetSymbolAddress((void**)&o1,   g_o1);
    cudaGetSymbolAddress((void**)&Wk2e, g_Wk2e);
    cudaGetSymbolAddress((void**)&Wv2e, g_Wv2e);
    cudaGetSymbolAddress((void**)&bk2e, g_bk2e);
    cudaGetSymbolAddress((void**)&bv2e, g_bv2e);
    cudaGetSymbolAddress((void**)&u2,   g_u2);
    cudaGetSymbolAddress((void**)&w2,   g_w2);
    cudaGetSymbolAddress((void**)&T2,   g_T2);
    cudaGetSymbolAddress((void**)&S2,   g_S2);
    cudaGetSymbolAddress((void**)&bP2,  g_bP2);
    cudaGetSymbolAddress((void**)&P2,   g_P2);
    cudaGetSymbolAddress((void**)&b2,   g_b2);
    cudaGetSymbolAddress((void**)&W2,   g_W2);
    cudaGetSymbolAddress((void**)&W23,  g_W23);
    cudaGetSymbolAddress((void**)&b3,   g_b3);

    cudaFuncSetAttribute(tgemm, cudaFuncAttributeMaxDynamicSharedMemorySize, TG_SMEM);
    cudaFuncSetAttribute(tgemm_tn, cudaFuncAttributeMaxDynamicSharedMemorySize, TG_SMEM);

    const float inv_sa1 = 0.08838834764831845f;  // 1/sqrt(128)
    const float inv_sa2 = 0.125f;                // 1/sqrt(64)

    cudaStream_t sd;
    cudaStreamCreateWithFlags(&sd, cudaStreamNonBlocking);
    cudaEvent_t e0, eA, eS1, eB, eW1, eS2, eD2;
    cudaEventCreateWithFlags(&e0,   cudaEventDisableTiming);
    cudaEventCreateWithFlags(&eA,   cudaEventDisableTiming);
    cudaEventCreateWithFlags(&eS1,  cudaEventDisableTiming);
    cudaEventCreateWithFlags(&eB,   cudaEventDisableTiming);
    cudaEventCreateWithFlags(&eW1,  cudaEventDisableTiming);
    cudaEventCreateWithFlags(&eS2,  cudaEventDisableTiming);
    cudaEventCreateWithFlags(&eD2,  cudaEventDisableTiming);

    // ---- fork ----
    cudaEventRecord(e0, 0);
    cudaStreamWaitEvent(sd, e0, 0);

    // SIDE: s = colsum(x); u1 = s@Wk1, w1 = s@Wv1
    colsum<<<dim3(2), 256, 0, sd>>>(x, s);
    vecmat3<<<dim3(4, 16), 256, 0, sd>>>(s, 0, Wk1, (long long)DDIM*AD1, 0, 0,
                                         (const float*)nullptr, 0, u1, AD1,
                                         s, Wv1, nullptr, w1, 8, DDIM, AD1);
    cudaEventRecord(eA, sd);

    // MAIN: G = x^T x via tensor cores (split-K x8), T1 = G@Wv1, S1 partials
    tgemm_tn<<<dim3(4, 4, 8), 256, TG_SMEM>>>(x, 0, x, 0, Gp, DDIM, DDIM, NTOK);
    reduce8<<<dim3(1024, 1), 256>>>(Gp, G, 1.f, DDIM*DDIM);
    tgemm<<<dim3(1, 4, 8), 256, TG_SMEM>>>(G, 0, 0,
        Wv1, (const float*)nullptr, T1, NOSET2,
        (long long)DDIM*AD1, 0, 0,
        (long long)DDIM*AD1, 0, AD1, AD1, DDIM, 128, 0);
    gemm_tn_sk<<<dim3(2, 2, 64), 256>>>(Wk1, (long long)DDIM*AD1,
                                        T1, (long long)DDIM*AD1,
                                        Gp, AD1, AD1, DDIM);
    cudaStreamWaitEvent(0, eA, 0);
    reduceS<<<dim3(64, 8), 256>>>(Gp, S1, u1, bk1, w1, bv1,
                                  inv_sa1, AD1*AD1, AD1, AD1);
    cudaEventRecord(eS1, 0);

    // SIDE: bP1; b1; bk2e/bv2e
    cudaStreamWaitEvent(sd, eS1, 0);
    vecmat3<<<dim3(4, 64), 256, 0, sd>>>(bq1, AD1, S1, (long long)AD1*AD1, 0, 3,
                                         (const float*)nullptr, 0, bP1, AD1,
                                         NOVEC2, AD1, AD1);
    vecmat3<<<dim3(16, 8), 256, 0, sd>>>(bP1, NQH*AD1, Wo1, (long long)NQH*AD1*DDIM, 0, 0,
                                         bo1, DDIM, b1, DDIM, NOVEC2, NQH*AD1, DDIM);
    vecmat3<<<dim3(2, 16), 256, 0, sd>>>(b1, DDIM, Wk2, (long long)DDIM*AD2, 0, 0,
                                         bk2, AD2, bk2e, AD2,
                                         b1, Wv2, bv2, bv2e, 8, DDIM, AD2);
    cudaEventRecord(eB, sd);

    // MAIN: P1, W1 (record eW1)
    tgemm<<<dim3(1, 4, 64), 256, TG_SMEM>>>(Wq1, (long long)NQH*DDIM*AD1, (long long)DDIM*AD1,
        S1, (const float*)nullptr, P1, NOSET2,
        (long long)AD1*AD1, 0, 0,
        (long long)DDIM*NQH*AD1, AD1, NQH*AD1, AD1, AD1, 128, 3);
    tgemm<<<dim3(4, 4, 8), 256, TG_SMEM>>>(P1, (long long)DDIM*NQH*AD1, 0,
        Wo1, (const float*)nullptr, W1, NOSET2,
        (long long)NQH*AD1*DDIM, 0, 0,
        (long long)DDIM*DDIM, 0, DDIM, DDIM, NQH*AD1, 128, 0);
    cudaEventRecord(eW1, 0);

    // SIDE: o1 = x @ W1 + b1 (runs in the shadow of the tier-2 chain)
    cudaStreamWaitEvent(sd, eW1, 0);
    tgemm<<<dim3(4, 16, 8), 256, TG_SMEM, sd>>>(x, 0, 0,
        W1, b1, o1, NOSET2,
        (long long)DDIM*DDIM, 0, DDIM,
        (long long)NTOK*DDIM, 0, DDIM, DDIM, DDIM, 128, 0);

    // MAIN: Wk2e/Wv2e, u2w2, T2, S2 partials, reduceS S2
    tgemm<<<dim3(1, 4, 16), 256, TG_SMEM>>>(W1, (long long)DDIM*DDIM, 0,
        Wk2, (const float*)nullptr, Wk2e,
        Wv2, (const float*)nullptr, Wv2e, 8,
        (long long)DDIM*AD2, 0, 0,
        (long long)DDIM*AD2, 0, AD2, AD2, DDIM, 64, 0);
    vecmat3<<<dim3(2, 16), 256>>>(s, 0, Wk2e, (long long)DDIM*AD2, 0, 0,
                                  (const float*)nullptr, 0, u2, AD2,
                                  s, Wv2e, nullptr, w2, 8, DDIM, AD2);
    tgemm<<<dim3(1, 4, 8), 256, TG_SMEM>>>(G, 0, 0,
        Wv2e, (const float*)nullptr, T2, NOSET2,
        (long long)DDIM*AD2, 0, 0,
        (long long)DDIM*AD2, 0, AD2, AD2, DDIM, 64, 0);
    gemm_tn_sk<<<dim3(1, 1, 64), 256>>>(Wk2e, (long long)DDIM*AD2,
                                        T2, (long long)DDIM*AD2,
                                        Gp, AD2, AD2, DDIM);
    cudaStreamWaitEvent(0, eB, 0);
    reduceS<<<dim3(16, 8), 256>>>(Gp, S2, u2, bk2e, w2, bv2e,
                                  inv_sa2, AD2*AD2, AD2, AD2);
    cudaEventRecord(eS2, 0);

    // SIDE: bP2, b2, b3 (after o1 — side stream is serial), record eD2
    cudaStreamWaitEvent(sd, eS2, 0);
    vecmat3<<<dim3(2, 64), 256, 0, sd>>>(bq2, AD2, S2, (long long)AD2*AD2, 0, 3,
                                         (const float*)nullptr, 0, bP2, AD2,
                                         NOVEC2, AD2, AD2);
    vecmat3<<<dim3(16, 8), 256, 0, sd>>>(bP2, NQH*AD2, Wo2, (long long)NQH*AD2*DDIM, 0, 0,
                                         bo2, DDIM, b2, DDIM, NOVEC2, NQH*AD2, DDIM);
    vecmat3<<<dim3(16, 8), 256, 0, sd>>>(b2, DDIM, Wo, 0, 0, 0,
                                         bo, 0, b3, DDIM, NOVEC2, DDIM, DDIM);
    cudaEventRecord(eD2, sd);

    // MAIN: P2, W2, W23
    tgemm<<<dim3(1, 4, 64), 256, TG_SMEM>>>(Wq2, (long long)NQH*DDIM*AD2, (long long)DDIM*AD2,
        S2, (const float*)nullptr, P2, NOSET2,
        (long long)AD2*AD2, 0, 0,
        (long long)DDIM*NQH*AD2, AD2, NQH*AD2, AD2, AD2, 64, 3);
    tgemm<<<dim3(4, 4, 8), 256, TG_SMEM>>>(P2, (long long)DDIM*NQH*AD2, 0,
        Wo2, (const float*)nullptr, W2, NOSET2,
        (long long)NQH*AD2*DDIM, 0, 0,
        (long long)DDIM*DDIM, 0, DDIM, DDIM, NQH*AD2, 128, 0);
    tgemm<<<dim3(4, 4, 8), 256, TG_SMEM>>>(W2, (long long)DDIM*DDIM, 0,
        Wo, (const float*)nullptr, W23, NOSET2,
        0, 0, 0,
        (long long)DDIM*DDIM, 0, DDIM, DDIM, DDIM, 128, 0);

    // MAIN: join (o1 + b3 from side); out = o1 @ W23 + b3
    cudaStreamWaitEvent(0, eD2, 0);
    tgemm<<<dim3(4, 16, 8), 256, TG_SMEM>>>(o1, (long long)NTOK*DDIM, 0,
        W23, b3, out, NOSET2,
        (long long)DDIM*DDIM, 0, DDIM,
        (long long)NTOK*DDIM, 0, DDIM, DDIM, DDIM, 128, 0);
}

// round 11
// speedup vs baseline: 1.1417x; 1.1417x over previous
#include <cuda_runtime.h>
#include <cuda_bf16.h>
#include <stdint.h>

// ---- problem constants ----
#define NTOK 2048
#define DDIM 512
#define GRP  8
#define NQH  8
#define AD1  128
#define AD2  64

// ---- scratch (device globals: allocation-free) ----
__device__ float g_Gp[8*DDIM*DDIM];
__device__ float g_G[DDIM*DDIM];
__device__ float g_s[DDIM];
__device__ float g_u1[GRP*AD1];
__device__ float g_w1[GRP*AD1];
__device__ float g_S1[GRP*AD1*AD1];
__device__ float g_T1[GRP*DDIM*AD1];
__device__ float g_P1[GRP*DDIM*NQH*AD1];
__device__ float g_bP1[GRP*NQH*AD1];
__device__ float g_W1[GRP*DDIM*DDIM];
__device__ float g_b1[GRP*DDIM];
__device__ float g_Wo1k[GRP*NQH*AD1*AD2];
__device__ float g_Wo1v[GRP*NQH*AD1*AD2];
__device__ float g_bo1k[GRP*AD2];
__device__ float g_bo1v[GRP*AD2];
__device__ float g_Wo2e[GRP*DDIM*DDIM];
__device__ float g_bo3[GRP*DDIM];
__device__ float g_Wk2e[GRP*DDIM*AD2];
__device__ float g_Wv2e[GRP*DDIM*AD2];
__device__ float g_bk2e[GRP*AD2];
__device__ float g_bv2e[GRP*AD2];
__device__ float g_u2[GRP*AD2];
__device__ float g_w2[GRP*AD2];
__device__ float g_T2[GRP*DDIM*AD2];
__device__ float g_S2[GRP*AD2*AD2];
__device__ float g_bP2[GRP*NQH*AD2];
__device__ float g_P2[GRP*DDIM*NQH*AD2];
__device__ float g_W23[GRP*DDIM*DDIM];
__device__ float g_Wf[GRP*DDIM*DDIM];
__device__ float g_b3[GRP*DDIM];
__device__ float g_bf[GRP*DDIM];

// ---- helpers ----
__device__ __forceinline__ uint32_t smem_u32(const void* p) {
    return (uint32_t)__cvta_generic_to_shared(p);
}
__device__ __forceinline__ uint32_t sw128(uint32_t off) {
    return off ^ ((off >> 3) & 0x70);
}
__device__ __forceinline__ uint32_t lds32(uint32_t a) {
    uint32_t v;
    asm volatile("ld.shared.b32 %0, [%1];" : "=r"(v) : "r"(a));
    return v;
}
__device__ __forceinline__ uint32_t lds32lo(uint32_t a) {
    uint32_t v;
    asm volatile("ld.shared.b32 %0, [%1+16384];" : "=r"(v) : "r"(a));
    return v;
}
__device__ __forceinline__ void sts64(uint32_t a, uint2 v) {
    asm volatile("st.shared.v2.b32 [%0], {%1,%2};"
                 :: "r"(a), "r"(v.x), "r"(v.y));
}
__device__ __forceinline__ void split4(float4 f, uint2& hi, uint2& lo) {
    float a[4] = {f.x, f.y, f.z, f.w};
    unsigned h[4], l[4];
#pragma unroll
    for (int i = 0; i < 4; i++) {
        __nv_bfloat16 bh = __float2bfloat16(a[i]);
        float r = a[i] - __bfloat162float(bh);
        __nv_bfloat16 bl = __float2bfloat16(r);
        h[i] = (unsigned)__bfloat16_as_ushort(bh);
        l[i] = (unsigned)__bfloat16_as_ushort(bl);
    }
    hi = make_uint2(h[0] | (h[1] << 16), h[2] | (h[3] << 16));
    lo = make_uint2(l[0] | (l[1] << 16), l[2] | (l[3] << 16));
}
#define MMA16816(c, a0, a1, a2, a3, b0, b1) \
    asm volatile( \
        "mma.sync.aligned.m16n8k16.row.col.f32.bf16.bf16.f32 " \
        "{%0,%1,%2,%3}, {%4,%5,%6,%7}, {%8,%9}, {%0,%1,%2,%3};" \
        : "+f"((c)[0]), "+f"((c)[1]), "+f"((c)[2]), "+f"((c)[3]) \
        : "r"(a0), "r"(a1), "r"(a2), "r"(a3), "r"(b0), "r"(b1))

#define OFF_B 32768
#define OFF_STAGE 65536
#define STAGE_BYTES (64 * 132 * 4)
#define TG_SMEM (1024 + OFF_STAGE + STAGE_BYTES)

// ============================================================================
// Batched tensor-core GEMM (bf16 hi/lo split, fp32 in/out), coalesced fills.
// ============================================================================
__global__ __launch_bounds__(256)
void tgemm(const float* __restrict__ A, long long aO, long long aI,
           const float* __restrict__ B, const float* __restrict__ bias,
           float* __restrict__ C,
           const float* __restrict__ B2, const float* __restrict__ bias2,
           float* __restrict__ C2, int zsplit,
           long long bO, long long bI, long long biasO,
           long long cO, long long cI, int ldc,
           int N, int K, int ntile, int bshift)
{
    extern __shared__ char smraw[];
    uint32_t sb0 = smem_u32(smraw);
    uint32_t abase = (sb0 + 1023) & ~1023u;
    char* tiles = smraw + (abase - sb0);
    float* stage = (float*)(tiles + OFF_STAGE);

    int tid = threadIdx.x;
    int lane = tid & 31, w = tid >> 5;
    int gid = lane >> 2, tig = lane & 3;

    int z = blockIdx.z;
    const float* Bu = B; const float* biasu = bias; float* Cu = C;
    if (z >= zsplit) { z -= zsplit; Bu = B2; biasu = bias2; Cu = C2; }
    int bh = z >> bshift, bl = z & ((1 << bshift) - 1);
    const float* Ab = A + (long long)bh * aO + (long long)bl * aI;
    const float* Bb = Bu + (long long)bh * bO + (long long)bl * bI;
    float*       Cb = Cu + (long long)bh * cO + (long long)bl * cI;

    int m0 = blockIdx.y * 128;
    int n0b = blockIdx.x * ntile;

    int wm = w & 1, wn = w >> 1;
    int warp_m = wm * 64;
    int warp_n = wn * (ntile >> 2);
    int Ntiles = ntile >> 5;

    int SSTR = ntile + 4;
    int nf4B = (ntile == 128) ? 8 : 4;
    int bsh  = (ntile == 128) ? 5 : 4;
    int p2n, p2k0, p2cnt;
    if (ntile == 128) { p2n = (w & 3) * 32 + lane; p2k0 = (w >> 2) * 32; p2cnt = 32; }
    else              { p2n = (w & 1) * 32 + lane; p2k0 = (w >> 1) * 16; p2cnt = 16; }

    float acc[4][4][4];
#pragma unroll
    for (int i = 0; i < 4; i++)
#pragma unroll
        for (int j = 0; j < 4; j++)
#pragma unroll
            for (int k = 0; k < 4; k++) acc[i][j][k] = 0.f;

    uint32_t aB[4], bB[4];
#pragma unroll
    for (int mt = 0; mt < 4; mt++)
        aB[mt] = abase + (uint32_t)(warp_m + mt * 16 + gid) * 128;
#pragma unroll
    for (int nt = 0; nt < 4; nt++)
        bB[nt] = abase + OFF_B + (uint32_t)(warp_n + nt * 8 + gid) * 128;
    uint32_t rx = (uint32_t)gid << 4;

    int nchunk = K >> 6;
    for (int ch = 0; ch < nchunk; ch++) {
        int kc = ch << 6;
        if (ch) __syncthreads();

#pragma unroll
        for (int i = 0; i < 8; i++) {
            int flat = tid + (i << 8);
            int row = flat >> 4;
            int c4 = (flat & 15) << 2;
            float4 f = *(const float4*)(Ab + (long long)(m0 + row) * K + kc + c4);
            uint2 hi, lo;
            split4(f, hi, lo);
            uint32_t sw = abase + sw128((uint32_t)row * 128 + c4 * 2);
            sts64(sw, hi);
            sts64(sw + 16384, lo);
        }
        for (int i = 0; i < nf4B; i++) {
            int flat = tid + (i << 8);
            int k = flat >> bsh;
            int c4 = (flat & ((1 << bsh) - 1)) << 2;
            float4 f = *(const float4*)(Bb + (long long)(kc + k) * N + n0b + c4);
            *(float4*)(stage + k * SSTR + c4) = f;
        }
        __syncthreads();
        for (int k = p2k0; k < p2k0 + p2cnt; k += 4) {
            float4 f = make_float4(stage[k * SSTR + p2n],
                                   stage[(k + 1) * SSTR + p2n],
                                   stage[(k + 2) * SSTR + p2n],
                                   stage[(k + 3) * SSTR + p2n]);
            uint2 hi, lo;
            split4(f, hi, lo);
            uint32_t sw = abase + OFF_B + sw128((uint32_t)p2n * 128 + k * 2);
            sts64(sw, hi);
            sts64(sw + 16384, lo);
        }
        __syncthreads();

#pragma unroll
        for (int ks = 0; ks < 4; ks++) {
            uint32_t q0 = ((uint32_t)(ks * 32) + (uint32_t)tig * 4) ^ rx;
            uint32_t q1 = q0 ^ 16;
            uint32_t ah[4][4], al[4][4];
#pragma unroll
            for (int mt = 0; mt < 4; mt++) {
                uint32_t base = aB[mt];
                ah[mt][0] = lds32(base + q0);
                ah[mt][1] = lds32(base + 1024 + q0);
                ah[mt][2] = lds32(base + q1);
                ah[mt][3] = lds32(base + 1024 + q1);
                al[mt][0] = lds32lo(base + q0);
                al[mt][1] = lds32lo(base + 1024 + q0);
                al[mt][2] = lds32lo(base + q1);
                al[mt][3] = lds32lo(base + 1024 + q1);
            }
#pragma unroll
            for (int nt = 0; nt < 4; nt++) {
                if (nt >= Ntiles) break;
                uint32_t bb = bB[nt];
                uint32_t bh0 = lds32(bb + q0);
                uint32_t bh1 = lds32(bb + q1);
                uint32_t bl0 = lds32lo(bb + q0);
                uint32_t bl1 = lds32lo(bb + q1);
#pragma unroll
                for (int mt = 0; mt < 4; mt++) {
                    MMA16816(acc[mt][nt], ah[mt][0], ah[mt][1], ah[mt][2], ah[mt][3], bh0, bh1);
                    MMA16816(acc[mt][nt], ah[mt][0], ah[mt][1], ah[mt][2], ah[mt][3], bl0, bl1);
                    MMA16816(acc[mt][nt], al[mt][0], al[mt][1], al[mt][2], al[mt][3], bh0, bh1);
                }
            }
        }
    }

    const float* bp = biasu ? (biasu + (long long)bh * biasO + n0b) : (const float*)nullptr;
#pragma unroll
    for (int mt = 0; mt < 4; mt++) {
        long long r0 = m0 + warp_m + mt * 16 + gid;
#pragma unroll
        for (int nt = 0; nt < 4; nt++) {
            if (nt >= Ntiles) break;
            int cc = warp_n + nt * 8 + 2 * tig;
            float b0 = 0.f, b1 = 0.f;
            if (bp) { b0 = bp[cc]; b1 = bp[cc + 1]; }
            float2 v0 = make_float2(acc[mt][nt][0] + b0, acc[mt][nt][1] + b1);
            float2 v1 = make_float2(acc[mt][nt][2] + b0, acc[mt][nt][3] + b1);
            *(float2*)&Cb[r0 * ldc + n0b + cc]       = v0;
            *(float2*)&Cb[(r0 + 8) * ldc + n0b + cc] = v1;
        }
    }
}

// ============================================================================
// TN tensor-core GEMM, split-K x8 partials: Cp[z] = A_slice^T @ B_slice.
// ============================================================================
__global__ __launch_bounds__(256)
void tgemm_tn(const float* __restrict__ A, long long aO,
              const float* __restrict__ B, long long bO,
              float* __restrict__ Cp, int M, int N, int Ktot)
{
    extern __shared__ char smraw[];
    uint32_t sb0 = smem_u32(smraw);
    uint32_t abase = (sb0 + 1023) & ~1023u;
    char* tiles = smraw + (abase - sb0);
    float* stage = (float*)(tiles + OFF_STAGE);

    int tid = threadIdx.x;
    int lane = tid & 31, w = tid >> 5;
    int gid = lane >> 2, tig = lane & 3;

    int z = blockIdx.z;
    int g = z >> 3, c = z & 7;
    int kl = Ktot >> 3;
    const float* Ab = A + (long long)g * aO + (long long)c * kl * M;
    const float* Bb = B + (long long)g * bO + (long long)c * kl * N;
    float*       Cb = Cp + (long long)z * M * N;

    int m0 = blockIdx.y * 128;
    int n0b = blockIdx.x * 128;

    int wm = w & 1, wn = w >> 1;
    int warp_m = wm * 64;
    int warp_n = wn * 32;

    int p2n = (w & 3) * 32 + lane;
    int p2k0 = (w >> 2) * 32;

    float acc[4][4][4];
#pragma unroll
    for (int i = 0; i < 4; i++)
#pragma unroll
        for (int j = 0; j < 4; j++)
#pragma unroll
            for (int k = 0; k < 4; k++) acc[i][j][k] = 0.f;

    uint32_t aB[4], bB[4];
#pragma unroll
    for (int mt = 0; mt < 4; mt++)
        aB[mt] = abase + (uint32_t)(warp_m + mt * 16 + gid) * 128;
#pragma unroll
    for (int nt = 0; nt < 4; nt++)
        bB[nt] = abase + OFF_B + (uint32_t)(warp_n + nt * 8 + gid) * 128;
    uint32_t rx = (uint32_t)gid << 4;

    int nchunk = kl >> 6;
    for (int ch = 0; ch < nchunk; ch++) {
        int kc = ch << 6;
        if (ch) __syncthreads();

#pragma unroll
        for (int i = 0; i < 8; i++) {
            int flat = tid + (i << 8);
            int k = flat >> 5;
            int c4 = (flat & 31) << 2;
            float4 f = *(const float4*)(Ab + (long long)(kc + k) * M + m0 + c4);
            *(float4*)(stage + k * 132 + c4) = f;
        }
        __syncthreads();
        for (int k = p2k0; k < p2k0 + 32; k += 4) {
            float4 f = make_float4(stage[k * 132 + p2n],
                                   stage[(k + 1) * 132 + p2n],
                                   stage[(k + 2) * 132 + p2n],
                                   stage[(k + 3) * 132 + p2n]);
            uint2 hi, lo;
            split4(f, hi, lo);
            uint32_t sw = abase + sw128((uint32_t)p2n * 128 + k * 2);
            sts64(sw, hi);
            sts64(sw + 16384, lo);
        }
        __syncthreads();
#pragma unroll
        for (int i = 0; i < 8; i++) {
            int flat = tid + (i << 8);
            int k = flat >> 5;
            int c4 = (flat & 31) << 2;
            float4 f = *(const float4*)(Bb + (long long)(kc + k) * N + n0b + c4);
            *(float4*)(stage + k * 132 + c4) = f;
        }
        __syncthreads();
        for (int k = p2k0; k < p2k0 + 32; k += 4) {
            float4 f = make_float4(stage[k * 132 + p2n],
                                   stage[(k + 1) * 132 + p2n],
                                   stage[(k + 2) * 132 + p2n],
                                   stage[(k + 3) * 132 + p2n]);
            uint2 hi, lo;
            split4(f, hi, lo);
            uint32_t sw = abase + OFF_B + sw128((uint32_t)p2n * 128 + k * 2);
            sts64(sw, hi);
            sts64(sw + 16384, lo);
        }
        __syncthreads();

#pragma unroll
        for (int ks = 0; ks < 4; ks++) {
            uint32_t q0 = ((uint32_t)(ks * 32) + (uint32_t)tig * 4) ^ rx;
            uint32_t q1 = q0 ^ 16;
            uint32_t ah[4][4], al[4][4];
#pragma unroll
            for (int mt = 0; mt < 4; mt++) {
                uint32_t base = aB[mt];
                ah[mt][0] = lds32(base + q0);
                ah[mt][1] = lds32(base + 1024 + q0);
                ah[mt][2] = lds32(base + q1);
                ah[mt][3] = lds32(base + 1024 + q1);
                al[mt][0] = lds32lo(base + q0);
                al[mt][1] = lds32lo(base + 1024 + q0);
                al[mt][2] = lds32lo(base + q1);
                al[mt][3] = lds32lo(base + 1024 + q1);
            }
#pragma unroll
            for (int nt = 0; nt < 4; nt++) {
                uint32_t bb = bB[nt];
                uint32_t bh0 = lds32(bb + q0);
                uint32_t bh1 = lds32(bb + q1);
                uint32_t bl0 = lds32lo(bb + q0);
                uint32_t bl1 = lds32lo(bb + q1);
#pragma unroll
                for (int mt = 0; mt < 4; mt++) {
                    MMA16816(acc[mt][nt], ah[mt][0], ah[mt][1], ah[mt][2], ah[mt][3], bh0, bh1);
                    MMA16816(acc[mt][nt], ah[mt][0], ah[mt][1], ah[mt][2], ah[mt][3], bl0, bl1);
                    MMA16816(acc[mt][nt], al[mt][0], al[mt][1], al[mt][2], al[mt][3], bh0, bh1);
                }
            }
        }
    }

#pragma unroll
    for (int mt = 0; mt < 4; mt++) {
        long long r0 = m0 + warp_m + mt * 16 + gid;
#pragma unroll
        for (int nt = 0; nt < 4; nt++) {
            int cc = warp_n + nt * 8 + 2 * tig;
            float2 v0 = make_float2(acc[mt][nt][0], acc[mt][nt][1]);
            float2 v1 = make_float2(acc[mt][nt][2], acc[mt][nt][3]);
            *(float2*)&Cb[r0 * N + n0b + cc]       = v0;
            *(float2*)&Cb[(r0 + 8) * N + n0b + cc] = v1;
        }
    }
}

// ============================================================================
// Split-K TN GEMM partials (fp32): Cp[z] = A_slice^T @ B_slice
// ============================================================================
__global__ __launch_bounds__(256)
void gemm_tn_sk(const float* __restrict__ A, long long aO,
                const float* __restrict__ B, long long bO,
                float* __restrict__ Cp, int M, int N, int Ktot)
{
    int z = blockIdx.z;
    int g = z >> 3, c = z & 7;
    int kl = Ktot >> 3;
    const float* Ab = A + (long long)g * aO + (long long)c * kl * M;
    const float* Bb = B + (long long)g * bO + (long long)c * kl * N;
    float*       Cb = Cp + (long long)z * M * N;

    __shared__ __align__(16) float As[16][64];
    __shared__ __align__(16) float Bs[16][64];

    int tid = threadIdx.x;
    int m0 = blockIdx.y * 64;
    int n0 = blockIdx.x * 64;

    int lrow = tid >> 4;
    int lcol = (tid & 15) * 4;
    int tx = tid & 15;
    int ty = tid >> 4;

    const float* Ap = Ab + (long long)lrow * M + m0 + lcol;
    const float* Bp = Bb + (long long)lrow * N + n0 + lcol;

    float acc[4][4];
#pragma unroll
    for (int i = 0; i < 4; i++)
#pragma unroll
        for (int j = 0; j < 4; j++) acc[i][j] = 0.f;

    for (int k0 = 0; k0 < kl; k0 += 16) {
        *(float4*)&As[lrow][lcol] = *(const float4*)(Ap + (long long)k0 * M);
        *(float4*)&Bs[lrow][lcol] = *(const float4*)(Bp + (long long)k0 * N);
        __syncthreads();
#pragma unroll
        for (int kk = 0; kk < 16; kk++) {
            float4 a = *(const float4*)&As[kk][ty * 4];
            float4 bb4 = *(const float4*)&Bs[kk][tx * 4];
            float a4[4] = {a.x, a.y, a.z, a.w};
            float b4[4] = {bb4.x, bb4.y, bb4.z, bb4.w};
#pragma unroll
            for (int i = 0; i < 4; i++)
#pragma unroll
                for (int j = 0; j < 4; j++)
                    acc[i][j] = fmaf(a4[i], b4[j], acc[i][j]);
        }
        __syncthreads();
    }

#pragma unroll
    for (int i = 0; i < 4; i++) {
        int row = m0 + ty * 4 + i;
        float4 v = {acc[i][0], acc[i][1], acc[i][2], acc[i][3]};
        *(float4*)&Cb[(long long)row * N + n0 + tx * 4] = v;
    }
}

__global__ void reduce8(const float* __restrict__ Cp, float* __restrict__ C,
                        float alpha, int MN)
{
    int i = blockIdx.x * 256 + threadIdx.x;
    int g = blockIdx.y;
    const float* p = Cp + (long long)g * 8 * MN + i;
    float s = 0.f;
#pragma unroll
    for (int c = 0; c < 8; c++) s += p[(long long)c * MN];
    C[(long long)g * MN + i] = alpha * s;
}

__global__ void reduceS(const float* __restrict__ Cp, float* __restrict__ S,
                        const float* __restrict__ u, const float* __restrict__ bk,
                        const float* __restrict__ w, const float* __restrict__ bv,
                        float alpha, int MN, int M, int N)
{
    int i = blockIdx.x * 256 + threadIdx.x;
    int g = blockIdx.y;
    const float* p = Cp + (long long)g * 8 * MN + i;
    float ssum = 0.f;
#pragma unroll
    for (int c = 0; c < 8; c++) ssum += p[(long long)c * MN];
    int row = i / N, col = i - row * N;
    float uk = u[g * M + row], bki = bk[g * M + row];
    float wv = w[g * N + col], bvj = bv[g * N + col];
    ssum += uk * bvj + bki * wv + (float)NTOK * bki * bvj;
    S[(long long)g * MN + i] = alpha * ssum;
}

__global__ void colsum(const float* __restrict__ x, float* __restrict__ s)
{
    int c = blockIdx.x * 256 + threadIdx.x;
    float a0 = 0.f, a1 = 0.f, a2 = 0.f, a3 = 0.f;
    const float* p = x + c;
    for (int n = 0; n < NTOK; n += 4) {
        a0 += p[(long long)n * DDIM];
        a1 += p[(long long)(n + 1) * DDIM];
        a2 += p[(long long)(n + 2) * DDIM];
        a3 += p[(long long)(n + 3) * DDIM];
    }
    s[c] = (a0 + a1) + (a2 + a3);
}

// ============================================================================
// Batched vec @ mat: 8-way K-split x 32 cols per block; dual-set.
// ============================================================================
__global__ __launch_bounds__(256)
void vecmat3(const float* __restrict__ vec, long long vecStride,
             const float* __restrict__ mat, long long matO, long long matI, int bshift,
             const float* __restrict__ add, long long addStride,
             float* __restrict__ out, long long outStride,
             const float* __restrict__ vec2, const float* __restrict__ mat2,
             const float* __restrict__ add2, float* __restrict__ out2,
             int ysplit, int K, int N)
{
    int b = blockIdx.y;
    const float* vecu = vec; const float* matu = mat;
    const float* addu = add; float* outu = out;
    if (b >= ysplit) { b -= ysplit; vecu = vec2; matu = mat2; addu = add2; outu = out2; }
    int c = (threadIdx.x & 31) + blockIdx.x * 32;
    int s = threadIdx.x >> 5;
    const float* v = vecu + (long long)b * vecStride;
    const float* m = matu + (long long)(b >> bshift) * matO
                          + (long long)(b & ((1 << bshift) - 1)) * matI;
    int kpart = K >> 3;
    int kb = s * kpart;
    float a0 = 0.f, a1 = 0.f, a2 = 0.f, a3 = 0.f;
    if (c < N) {
        const float* mp = m + (long long)kb * N + c;
        const float* vp = v + kb;
        for (int k = 0; k < kpart; k += 4) {
            a0 = fmaf(vp[k],     mp[(long long)k * N], a0);
            a1 = fmaf(vp[k + 1], mp[(long long)(k + 1) * N], a1);
            a2 = fmaf(vp[k + 2], mp[(long long)(k + 2) * N], a2);
            a3 = fmaf(vp[k + 3], mp[(long long)(k + 3) * N], a3);
        }
    }
    __shared__ float red[256];
    red[threadIdx.x] = (a0 + a1) + (a2 + a3);
    __syncthreads();
    if (s == 0 && c < N) {
        float t = 0.f;
#pragma unroll
        for (int i = 0; i < 8; i++) t += red[threadIdx.x + i * 32];
        if (addu) t += addu[(long long)b * addStride + c];
        outu[(long long)b * outStride + c] = t;
    }
}

#define NOSET2 (const float*)nullptr, (const float*)nullptr, (float*)nullptr, (1<<30)
#define NOVEC2 nullptr, nullptr, nullptr, nullptr, (1<<30)

extern "C" void kernel_launch(void* const* d_in, const int* in_sizes, int n_in,
                              void* d_out, int out_size)
{
    (void)in_sizes; (void)n_in; (void)out_size;

    const float* x   = (const float*)d_in[0];
    const float* Wq1 = (const float*)d_in[1];
    const float* bq1 = (const float*)d_in[2];
    const float* Wk1 = (const float*)d_in[3];
    const float* bk1 = (const float*)d_in[4];
    const float* Wv1 = (const float*)d_in[5];
    const float* bv1 = (const float*)d_in[6];
    const float* Wo1 = (const float*)d_in[7];
    const float* bo1 = (const float*)d_in[8];
    const float* Wq2 = (const float*)d_in[9];
    const float* bq2 = (const float*)d_in[10];
    const float* Wk2 = (const float*)d_in[11];
    const float* bk2 = (const float*)d_in[12];
    const float* Wv2 = (const float*)d_in[13];
    const float* bv2 = (const float*)d_in[14];
    const float* Wo2 = (const float*)d_in[15];
    const float* bo2 = (const float*)d_in[16];
    const float* Wo  = (const float*)d_in[17];
    const float* bo  = (const float*)d_in[18];
    float* out = (float*)d_out;

    float *Gp, *G, *s, *u1, *w1, *S1, *T1, *P1, *bP1, *W1, *b1;
    float *Wo1k, *Wo1v, *bo1k, *bo1v, *Wo2e, *bo3;
    float *Wk2e, *Wv2e, *bk2e, *bv2e, *u2, *w2, *T2, *S2, *bP2, *P2;
    float *W23, *Wf, *b3, *bf;
    cudaGetSymbolAddress((void**)&Gp,   g_Gp);
    cudaGetSymbolAddress((void**)&G,    g_G);
    cudaGetSymbolAddress((void**)&s,    g_s);
    cudaGetSymbolAddress((void**)&u1,   g_u1);
    cudaGetSymbolAddress((void**)&w1,   g_w1);
    cudaGetSymbolAddress((void**)&S1,   g_S1);
    cudaGetSymbolAddress((void**)&T1,   g_T1);
    cudaGetSymbolAddress((void**)&P1,   g_P1);
    cudaGetSymbolAddress((void**)&bP1,  g_bP1);
    cudaGetSymbolAddress((void**)&W1,   g_W1);
    cudaGetSymbolAddress((void**)&b1,   g_b1);
    cudaGetSymbolAddress((void**)&Wo1k, g_Wo1k);
    cudaGetSymbolAddress((void**)&Wo1v, g_Wo1v);
    cudaGetSymbolAddress((void**)&bo1k, g_bo1k);
    cudaGetSymbolAddress((void**)&bo1v, g_bo1v);
    cudaGetSymbolAddress((void**)&Wo2e, g_Wo2e);
    cudaGetSymbolAddress((void**)&bo3,  g_bo3);
    cudaGetSymbolAddress((void**)&Wk2e, g_Wk2e);
    cudaGetSymbolAddress((void**)&Wv2e, g_Wv2e);
    cudaGetSymbolAddress((void**)&bk2e, g_bk2e);
    cudaGetSymbolAddress((void**)&bv2e, g_bv2e);
    cudaGetSymbolAddress((void**)&u2,   g_u2);
    cudaGetSymbolAddress((void**)&w2,   g_w2);
    cudaGetSymbolAddress((void**)&T2,   g_T2);
    cudaGetSymbolAddress((void**)&S2,   g_S2);
    cudaGetSymbolAddress((void**)&bP2,  g_bP2);
    cudaGetSymbolAddress((void**)&P2,   g_P2);
    cudaGetSymbolAddress((void**)&W23,  g_W23);
    cudaGetSymbolAddress((void**)&Wf,   g_Wf);
    cudaGetSymbolAddress((void**)&b3,   g_b3);
    cudaGetSymbolAddress((void**)&bf,   g_bf);

    cudaFuncSetAttribute(tgemm, cudaFuncAttributeMaxDynamicSharedMemorySize, TG_SMEM);
    cudaFuncSetAttribute(tgemm_tn, cudaFuncAttributeMaxDynamicSharedMemorySize, TG_SMEM);

    const float inv_sa1 = 0.08838834764831845f;  // 1/sqrt(128)
    const float inv_sa2 = 0.125f;                // 1/sqrt(64)

    cudaStream_t sd;
    cudaStreamCreateWithFlags(&sd, cudaStreamNonBlocking);
    cudaEvent_t e0, eA, eS1, eP1, eK2, eWW1, eB, eS2, eW23, eD2;
    cudaEventCreateWithFlags(&e0,   cudaEventDisableTiming);
    cudaEventCreateWithFlags(&eA,   cudaEventDisableTiming);
    cudaEventCreateWithFlags(&eS1,  cudaEventDisableTiming);
    cudaEventCreateWithFlags(&eP1,  cudaEventDisableTiming);
    cudaEventCreateWithFlags(&eK2,  cudaEventDisableTiming);
    cudaEventCreateWithFlags(&eWW1, cudaEventDisableTiming);
    cudaEventCreateWithFlags(&eB,   cudaEventDisableTiming);
    cudaEventCreateWithFlags(&eS2,  cudaEventDisableTiming);
    cudaEventCreateWithFlags(&eW23, cudaEventDisableTiming);
    cudaEventCreateWithFlags(&eD2,  cudaEventDisableTiming);

    // ---- fork ----
    cudaEventRecord(e0, 0);
    cudaStreamWaitEvent(sd, e0, 0);

    // SIDE block 1: input-only precomputes
    colsum<<<dim3(2), 256, 0, sd>>>(x, s);
    vecmat3<<<dim3(4, 16), 256, 0, sd>>>(s, 0, Wk1, (long long)DDIM*AD1, 0, 0,
                                         (const float*)nullptr, 0, u1, AD1,
                                         s, Wv1, nullptr, w1, 8, DDIM, AD1);
    cudaEventRecord(eA, sd);
    // Wo1k/Wo1v = Wo1 @ Wk2 / Wv2   [1024,64] per g
    tgemm<<<dim3(1, 8, 16), 256, TG_SMEM, sd>>>(Wo1, (long long)NQH*AD1*DDIM, 0,
        Wk2, (const float*)nullptr, Wo1k,
        Wv2, (const float*)nullptr, Wo1v, 8,
        (long long)DDIM*AD2, 0, 0,
        (long long)NQH*AD1*AD2, 0, AD2, AD2, DDIM, 64, 0);
    // bo1k/bo1v = bo1 @ Wk2 + bk2 / bo1 @ Wv2 + bv2
    vecmat3<<<dim3(2, 16), 256, 0, sd>>>(bo1, DDIM, Wk2, (long long)DDIM*AD2, 0, 0,
                                         bk2, AD2, bo1k, AD2,
                                         bo1, Wv2, bv2, bo1v, 8, DDIM, AD2);
    // Wo2e = Wo2 @ Wo   [512,512] per g
    tgemm<<<dim3(4, 4, 8), 256, TG_SMEM, sd>>>(Wo2, (long long)NQH*AD2*DDIM, 0,
        Wo, (const float*)nullptr, Wo2e, NOSET2,
        0, 0, 0,
        (long long)DDIM*DDIM, 0, DDIM, DDIM, NQH*AD2, 128, 0);
    // bo3 = bo2 @ Wo + bo
    vecmat3<<<dim3(16, 8), 256, 0, sd>>>(bo2, DDIM, Wo, 0, 0, 0,
                                         bo, 0, bo3, DDIM, NOVEC2, DDIM, DDIM);

    // MAIN block 1: G = x^T x (tensor-core split-K), T1, S1
    tgemm_tn<<<dim3(4, 4, 8), 256, TG_SMEM>>>(x, 0, x, 0, Gp, DDIM, DDIM, NTOK);
    reduce8<<<dim3(1024, 1), 256>>>(Gp, G, 1.f, DDIM*DDIM);
    tgemm<<<dim3(1, 4, 8), 256, TG_SMEM>>>(G, 0, 0,
        Wv1, (const float*)nullptr, T1, NOSET2,
        (long long)DDIM*AD1, 0, 0,
        (long long)DDIM*AD1, 0, AD1, AD1, DDIM, 128, 0);
    gemm_tn_sk<<<dim3(2, 2, 64), 256>>>(Wk1, (long long)DDIM*AD1,
                                        T1, (long long)DDIM*AD1,
                                        Gp, AD1, AD1, DDIM);
    cudaStreamWaitEvent(0, eA, 0);
    reduceS<<<dim3(64, 8), 256>>>(Gp, S1, u1, bk1, w1, bv1,
                                  inv_sa1, AD1*AD1, AD1, AD1);
    cudaEventRecord(eS1, 0);

    // SIDE block 2: bP1; b1 = bP1@Wo1 + bo1; bk2e/bv2e = bP1@Wo1k/v + bo1k/v
    cudaStreamWaitEvent(sd, eS1, 0);
    vecmat3<<<dim3(4, 64), 256, 0, sd>>>(bq1, AD1, S1, (long long)AD1*AD1, 0, 3,
                                         (const float*)nullptr, 0, bP1, AD1,
                                         NOVEC2, AD1, AD1);
    vecmat3<<<dim3(16, 8), 256, 0, sd>>>(bP1, NQH*AD1, Wo1, (long long)NQH*AD1*DDIM, 0, 0,
                                         bo1, DDIM, b1, DDIM, NOVEC2, NQH*AD1, DDIM);
    vecmat3<<<dim3(2, 16), 256, 0, sd>>>(bP1, NQH*AD1, Wo1k, (long long)NQH*AD1*AD2, 0, 0,
                                         bo1k, AD2, bk2e, AD2,
                                         bP1, Wo1v, bo1v, bv2e, 8, NQH*AD1, AD2);

    // MAIN block 2: P1; Wk2e/Wv2e = P1cat @ Wo1k/v; T2; S2 partials
    tgemm<<<dim3(1, 4, 64), 256, TG_SMEM>>>(Wq1, (long long)NQH*DDIM*AD1, (long long)DDIM*AD1,
        S1, (const float*)nullptr, P1, NOSET2,
        (long long)AD1*AD1, 0, 0,
        (long long)DDIM*NQH*AD1, AD1, NQH*AD1, AD1, AD1, 128, 3);
    cudaEventRecord(eP1, 0);
    tgemm<<<dim3(1, 4, 16), 256, TG_SMEM>>>(P1, (long long)DDIM*NQH*AD1, 0,
        Wo1k, (const float*)nullptr, Wk2e,
        Wo1v, (const float*)nullptr, Wv2e, 8,
        (long long)NQH*AD1*AD2, 0, 0,
        (long long)DDIM*AD2, 0, AD2, AD2, NQH*AD1, 64, 0);
    cudaEventRecord(eK2, 0);
    tgemm<<<dim3(1, 4, 8), 256, TG_SMEM>>>(G, 0, 0,
        Wv2e, (const float*)nullptr, T2, NOSET2,
        (long long)DDIM*AD2, 0, 0,
        (long long)DDIM*AD2, 0, AD2, AD2, DDIM, 64, 0);
    gemm_tn_sk<<<dim3(1, 1, 64), 256>>>(Wk2e, (long long)DDIM*AD2,
                                        T2, (long long)DDIM*AD2,
                                        Gp, AD2, AD2, DDIM);

    // SIDE block 3: W1 = P1cat @ Wo1 (shadow); u2/w2 = s @ Wk2e/Wv2e
    cudaStreamWaitEvent(sd, eP1, 0);
    tgemm<<<dim3(4, 4, 8), 256, TG_SMEM, sd>>>(P1, (long long)DDIM*NQH*AD1, 0,
        Wo1, (const float*)nullptr, W1, NOSET2,
        (long long)NQH*AD1*DDIM, 0, 0,
        (long long)DDIM*DDIM, 0, DDIM, DDIM, NQH*AD1, 128, 0);
    cudaEventRecord(eWW1, sd);
    cudaStreamWaitEvent(sd, eK2, 0);
    vecmat3<<<dim3(2, 16), 256, 0, sd>>>(s, 0, Wk2e, (long long)DDIM*AD2, 0, 0,
                                         (const float*)nullptr, 0, u2, AD2,
                                         s, Wv2e, nullptr, w2, 8, DDIM, AD2);
    cudaEventRecord(eB, sd);

    // MAIN block 3: reduceS S2; P2; W23 = P2cat@Wo2e; Wf = W1@W23
    cudaStreamWaitEvent(0, eB, 0);
    reduceS<<<dim3(16, 8), 256>>>(Gp, S2, u2, bk2e, w2, bv2e,
                                  inv_sa2, AD2*AD2, AD2, AD2);
    cudaEventRecord(eS2, 0);
    tgemm<<<dim3(1, 4, 64), 256, TG_SMEM>>>(Wq2, (long long)NQH*DDIM*AD2, (long long)DDIM*AD2,
        S2, (const float*)nullptr, P2, NOSET2,
        (long long)AD2*AD2, 0, 0,
        (long long)DDIM*NQH*AD2, AD2, NQH*AD2, AD2, AD2, 64, 3);
    tgemm<<<dim3(4, 4, 8), 256, TG_SMEM>>>(P2, (long long)DDIM*NQH*AD2, 0,
        Wo2e, (const float*)nullptr, W23, NOSET2,
        (long long)DDIM*DDIM, 0, 0,
        (long long)DDIM*DDIM, 0, DDIM, DDIM, NQH*AD2, 128, 0);
    cudaEventRecord(eW23, 0);
    cudaStreamWaitEvent(0, eWW1, 0);
    tgemm<<<dim3(4, 4, 8), 256, TG_SMEM>>>(W1, (long long)DDIM*DDIM, 0,
        W23, (const float*)nullptr, Wf, NOSET2,
        (long long)DDIM*DDIM, 0, 0,
        (long long)DDIM*DDIM, 0, DDIM, DDIM, DDIM, 128, 0);

    // SIDE block 4: bP2; b3 = bP2@Wo2e + bo3; bf = b1@W23 + b3
    cudaStreamWaitEvent(sd, eS2, 0);
    vecmat3<<<dim3(2, 64), 256, 0, sd>>>(bq2, AD2, S2, (long long)AD2*AD2, 0, 3,
                                         (const float*)nullptr, 0, bP2, AD2,
                                         NOVEC2, AD2, AD2);
    vecmat3<<<dim3(16, 8), 256, 0, sd>>>(bP2, NQH*AD2, Wo2e, (long long)DDIM*DDIM, 0, 0,
                                         bo3, DDIM, b3, DDIM, NOVEC2, NQH*AD2, DDIM);
    cudaStreamWaitEvent(sd, eW23, 0);
    vecmat3<<<dim3(16, 8), 256, 0, sd>>>(b1, DDIM, W23, (long long)DDIM*DDIM, 0, 0,
                                         b3, DDIM, bf, DDIM, NOVEC2, DDIM, DDIM);
    cudaEventRecord(eD2, sd);

    // MAIN: join; out = x @ Wf + bf
    cudaStreamWaitEvent(0, eD2, 0);
    tgemm<<<dim3(4, 16, 8), 256, TG_SMEM>>>(x, 0, 0,
        Wf, bf, out, NOSET2,
        (long long)DDIM*DDIM, 0, DDIM,
        (long long)NTOK*DDIM, 0, DDIM, DDIM, DDIM, 128, 0);
}

// round 12
// speedup vs baseline: 1.3302x; 1.1651x over previous
#include <cuda_runtime.h>
#include <cuda_bf16.h>
#include <stdint.h>

// ---- problem constants ----
#define NTOK 2048
#define DDIM 512
#define GRP  8
#define NQH  8
#define AD1  128
#define AD2  64

// ---- scratch (device globals: allocation-free) ----
__device__ float g_Gp[8*DDIM*DDIM];
__device__ float g_G[DDIM*DDIM];
__device__ float g_s[DDIM];
__device__ float g_u1[GRP*AD1];
__device__ float g_w1[GRP*AD1];
__device__ float g_S1[GRP*AD1*AD1];
__device__ float g_T1[GRP*DDIM*AD1];
__device__ float g_P1[GRP*DDIM*NQH*AD1];
__device__ float g_bP1[GRP*NQH*AD1];
__device__ float g_W1[GRP*DDIM*DDIM];
__device__ float g_b1[GRP*DDIM];
__device__ float g_Wo1k[GRP*NQH*AD1*AD2];
__device__ float g_Wo1v[GRP*NQH*AD1*AD2];
__device__ float g_bo1k[GRP*AD2];
__device__ float g_bo1v[GRP*AD2];
__device__ float g_Wo2e[GRP*DDIM*DDIM];
__device__ float g_bo3[GRP*DDIM];
__device__ float g_Wk2e[GRP*DDIM*AD2];
__device__ float g_Wv2e[GRP*DDIM*AD2];
__device__ float g_bk2e[GRP*AD2];
__device__ float g_bv2e[GRP*AD2];
__device__ float g_u2[GRP*AD2];
__device__ float g_w2[GRP*AD2];
__device__ float g_T2[GRP*DDIM*AD2];
__device__ float g_S2[GRP*AD2*AD2];
__device__ float g_bP2[GRP*NQH*AD2];
__device__ float g_P2[GRP*DDIM*NQH*AD2];
__device__ float g_W23[GRP*DDIM*DDIM];
__device__ float g_Wf[GRP*DDIM*DDIM];
__device__ float g_b3[GRP*DDIM];
__device__ float g_bf[GRP*DDIM];

// ---- helpers ----
__device__ __forceinline__ uint32_t smem_u32(const void* p) {
    return (uint32_t)__cvta_generic_to_shared(p);
}
__device__ __forceinline__ uint32_t sw128(uint32_t off) {
    return off ^ ((off >> 3) & 0x70);
}
__device__ __forceinline__ uint32_t lds32(uint32_t a) {
    uint32_t v;
    asm volatile("ld.shared.b32 %0, [%1];" : "=r"(v) : "r"(a));
    return v;
}
__device__ __forceinline__ uint32_t lds32lo(uint32_t a) {
    uint32_t v;
    asm volatile("ld.shared.b32 %0, [%1+16384];" : "=r"(v) : "r"(a));
    return v;
}
__device__ __forceinline__ void sts64(uint32_t a, uint2 v) {
    asm volatile("st.shared.v2.b32 [%0], {%1,%2};"
                 :: "r"(a), "r"(v.x), "r"(v.y));
}
__device__ __forceinline__ void split4(float4 f, uint2& hi, uint2& lo) {
    float a[4] = {f.x, f.y, f.z, f.w};
    unsigned h[4], l[4];
#pragma unroll
    for (int i = 0; i < 4; i++) {
        __nv_bfloat16 bh = __float2bfloat16(a[i]);
        float r = a[i] - __bfloat162float(bh);
        __nv_bfloat16 bl = __float2bfloat16(r);
        h[i] = (unsigned)__bfloat16_as_ushort(bh);
        l[i] = (unsigned)__bfloat16_as_ushort(bl);
    }
    hi = make_uint2(h[0] | (h[1] << 16), h[2] | (h[3] << 16));
    lo = make_uint2(l[0] | (l[1] << 16), l[2] | (l[3] << 16));
}
#define MMA16816(c, a0, a1, a2, a3, b0, b1) \
    asm volatile( \
        "mma.sync.aligned.m16n8k16.row.col.f32.bf16.bf16.f32 " \
        "{%0,%1,%2,%3}, {%4,%5,%6,%7}, {%8,%9}, {%0,%1,%2,%3};" \
        : "+f"((c)[0]), "+f"((c)[1]), "+f"((c)[2]), "+f"((c)[3]) \
        : "r"(a0), "r"(a1), "r"(a2), "r"(a3), "r"(b0), "r"(b1))

#define OFF_B 32768
#define OFF_STAGE 65536
#define STAGE_BYTES (64 * 132 * 4)
#define TG_SMEM (1024 + OFF_STAGE + STAGE_BYTES)

// ============================================================================
// Batched tensor-core GEMM (bf16 hi/lo split, fp32 in/out), coalesced fills,
// software-pipelined: next chunk's global loads prefetched into registers.
// ============================================================================
__global__ __launch_bounds__(256)
void tgemm(const float* __restrict__ A, long long aO, long long aI,
           const float* __restrict__ B, const float* __restrict__ bias,
           float* __restrict__ C,
           const float* __restrict__ B2, const float* __restrict__ bias2,
           float* __restrict__ C2, int zsplit,
           long long bO, long long bI, long long biasO,
           long long cO, long long cI, int ldc,
           int N, int K, int ntile, int bshift)
{
    extern __shared__ char smraw[];
    uint32_t sb0 = smem_u32(smraw);
    uint32_t abase = (sb0 + 1023) & ~1023u;
    char* tiles = smraw + (abase - sb0);
    float* stage = (float*)(tiles + OFF_STAGE);

    int tid = threadIdx.x;
    int lane = tid & 31, w = tid >> 5;
    int gid = lane >> 2, tig = lane & 3;

    int z = blockIdx.z;
    const float* Bu = B; const float* biasu = bias; float* Cu = C;
    if (z >= zsplit) { z -= zsplit; Bu = B2; biasu = bias2; Cu = C2; }
    int bh = z >> bshift, bl = z & ((1 << bshift) - 1);
    const float* Ab = A + (long long)bh * aO + (long long)bl * aI;
    const float* Bb = Bu + (long long)bh * bO + (long long)bl * bI;
    float*       Cb = Cu + (long long)bh * cO + (long long)bl * cI;

    int m0 = blockIdx.y * 128;
    int n0b = blockIdx.x * ntile;

    int wm = w & 1, wn = w >> 1;
    int warp_m = wm * 64;
    int warp_n = wn * (ntile >> 2);
    int Ntiles = ntile >> 5;

    int SSTR = ntile + 4;
    int nf4B = (ntile == 128) ? 8 : 4;
    int bsh  = (ntile == 128) ? 5 : 4;
    int p2n, p2k0, p2cnt;
    if (ntile == 128) { p2n = (w & 3) * 32 + lane; p2k0 = (w >> 2) * 32; p2cnt = 32; }
    else              { p2n = (w & 1) * 32 + lane; p2k0 = (w >> 1) * 16; p2cnt = 16; }

    // fill-side address precompute
    int arow = tid >> 4;
    int ac4 = (tid & 15) << 2;
    const float* ApBase = Ab + (long long)(m0 + arow) * K + ac4;   // + i*16 rows
    uint32_t aswb = abase + 0;  // sw applied per store

    float acc[4][4][4];
#pragma unroll
    for (int i = 0; i < 4; i++)
#pragma unroll
        for (int j = 0; j < 4; j++)
#pragma unroll
            for (int k = 0; k < 4; k++) acc[i][j][k] = 0.f;

    uint32_t aB[4], bB[4];
#pragma unroll
    for (int mt = 0; mt < 4; mt++)
        aB[mt] = abase + (uint32_t)(warp_m + mt * 16 + gid) * 128;
#pragma unroll
    for (int nt = 0; nt < 4; nt++)
        bB[nt] = abase + OFF_B + (uint32_t)(warp_n + nt * 8 + gid) * 128;
    uint32_t rx = (uint32_t)gid << 4;

    float4 pa[8], pb[8];
    // prologue: prefetch chunk 0
#pragma unroll
    for (int i = 0; i < 8; i++)
        pa[i] = *(const float4*)(ApBase + (long long)(i * 16) * K);
#pragma unroll
    for (int i = 0; i < 8; i++) if (i < nf4B) {
        int flat = tid + (i << 8);
        int k = flat >> bsh;
        int c4 = (flat & ((1 << bsh) - 1)) << 2;
        pb[i] = *(const float4*)(Bb + (long long)k * N + n0b + c4);
    }

    int nchunk = K >> 6;
    for (int ch = 0; ch < nchunk; ch++) {
        int kcn = (ch + 1) << 6;
        bool more = (ch + 1) < nchunk;

        // ---- store prefetched A to tiles ----
#pragma unroll
        for (int i = 0; i < 8; i++) {
            uint2 hi, lo;
            split4(pa[i], hi, lo);
            uint32_t sw = abase + sw128((uint32_t)(arow + i * 16) * 128 + ac4 * 2);
            sts64(sw, hi);
            sts64(sw + 16384, lo);
        }
        // ---- store prefetched B to stage ----
#pragma unroll
        for (int i = 0; i < 8; i++) if (i < nf4B) {
            int flat = tid + (i << 8);
            int k = flat >> bsh;
            int c4 = (flat & ((1 << bsh) - 1)) << 2;
            *(float4*)(stage + k * SSTR + c4) = pb[i];
        }
        __syncthreads();
        // ---- B pass 2: stage columns -> swizzled bf16 hi/lo tiles ----
        for (int k = p2k0; k < p2k0 + p2cnt; k += 4) {
            float4 f = make_float4(stage[k * SSTR + p2n],
                                   stage[(k + 1) * SSTR + p2n],
                                   stage[(k + 2) * SSTR + p2n],
                                   stage[(k + 3) * SSTR + p2n]);
            uint2 hi, lo;
            split4(f, hi, lo);
            uint32_t sw = abase + OFF_B + sw128((uint32_t)p2n * 128 + k * 2);
            sts64(sw, hi);
            sts64(sw + 16384, lo);
        }
        // ---- prefetch next chunk (overlaps with compute) ----
        if (more) {
#pragma unroll
            for (int i = 0; i < 8; i++)
                pa[i] = *(const float4*)(ApBase + (long long)(i * 16) * K + kcn);
#pragma unroll
            for (int i = 0; i < 8; i++) if (i < nf4B) {
                int flat = tid + (i << 8);
                int k = flat >> bsh;
                int c4 = (flat & ((1 << bsh) - 1)) << 2;
                pb[i] = *(const float4*)(Bb + (long long)(kcn + k) * N + n0b + c4);
            }
        }
        __syncthreads();

        // ---- compute: 4 k16 steps ----
#pragma unroll
        for (int ks = 0; ks < 4; ks++) {
            uint32_t q0 = ((uint32_t)(ks * 32) + (uint32_t)tig * 4) ^ rx;
            uint32_t q1 = q0 ^ 16;
            uint32_t ah[4][4], al[4][4];
#pragma unroll
            for (int mt = 0; mt < 4; mt++) {
                uint32_t base = aB[mt];
                ah[mt][0] = lds32(base + q0);
                ah[mt][1] = lds32(base + 1024 + q0);
                ah[mt][2] = lds32(base + q1);
                ah[mt][3] = lds32(base + 1024 + q1);
                al[mt][0] = lds32lo(base + q0);
                al[mt][1] = lds32lo(base + 1024 + q0);
                al[mt][2] = lds32lo(base + q1);
                al[mt][3] = lds32lo(base + 1024 + q1);
            }
#pragma unroll
            for (int nt = 0; nt < 4; nt++) {
                if (nt >= Ntiles) break;
                uint32_t bb = bB[nt];
                uint32_t bh0 = lds32(bb + q0);
                uint32_t bh1 = lds32(bb + q1);
                uint32_t bl0 = lds32lo(bb + q0);
                uint32_t bl1 = lds32lo(bb + q1);
#pragma unroll
                for (int mt = 0; mt < 4; mt++) {
                    MMA16816(acc[mt][nt], ah[mt][0], ah[mt][1], ah[mt][2], ah[mt][3], bh0, bh1);
                    MMA16816(acc[mt][nt], ah[mt][0], ah[mt][1], ah[mt][2], ah[mt][3], bl0, bl1);
                    MMA16816(acc[mt][nt], al[mt][0], al[mt][1], al[mt][2], al[mt][3], bh0, bh1);
                }
            }
        }
        if (more) __syncthreads();
    }

    const float* bp = biasu ? (biasu + (long long)bh * biasO + n0b) : (const float*)nullptr;
#pragma unroll
    for (int mt = 0; mt < 4; mt++) {
        long long r0 = m0 + warp_m + mt * 16 + gid;
#pragma unroll
        for (int nt = 0; nt < 4; nt++) {
            if (nt >= Ntiles) break;
            int cc = warp_n + nt * 8 + 2 * tig;
            float b0 = 0.f, b1 = 0.f;
            if (bp) { b0 = bp[cc]; b1 = bp[cc + 1]; }
            float2 v0 = make_float2(acc[mt][nt][0] + b0, acc[mt][nt][1] + b1);
            float2 v1 = make_float2(acc[mt][nt][2] + b0, acc[mt][nt][3] + b1);
            *(float2*)&Cb[r0 * ldc + n0b + cc]       = v0;
            *(float2*)&Cb[(r0 + 8) * ldc + n0b + cc] = v1;
        }
    }
}

// ============================================================================
// TN tensor-core GEMM, split-K x8 partials: Cp[z] = A_slice^T @ B_slice.
// ============================================================================
__global__ __launch_bounds__(256)
void tgemm_tn(const float* __restrict__ A, long long aO,
              const float* __restrict__ B, long long bO,
              float* __restrict__ Cp, int M, int N, int Ktot)
{
    extern __shared__ char smraw[];
    uint32_t sb0 = smem_u32(smraw);
    uint32_t abase = (sb0 + 1023) & ~1023u;
    char* tiles = smraw + (abase - sb0);
    float* stage = (float*)(tiles + OFF_STAGE);

    int tid = threadIdx.x;
    int lane = tid & 31, w = tid >> 5;
    int gid = lane >> 2, tig = lane & 3;

    int z = blockIdx.z;
    int g = z >> 3, c = z & 7;
    int kl = Ktot >> 3;
    const float* Ab = A + (long long)g * aO + (long long)c * kl * M;
    const float* Bb = B + (long long)g * bO + (long long)c * kl * N;
    float*       Cb = Cp + (long long)z * M * N;

    int m0 = blockIdx.y * 128;
    int n0b = blockIdx.x * 128;

    int wm = w & 1, wn = w >> 1;
    int warp_m = wm * 64;
    int warp_n = wn * 32;

    int p2n = (w & 3) * 32 + lane;
    int p2k0 = (w >> 2) * 32;

    float acc[4][4][4];
#pragma unroll
    for (int i = 0; i < 4; i++)
#pragma unroll
        for (int j = 0; j < 4; j++)
#pragma unroll
            for (int k = 0; k < 4; k++) acc[i][j][k] = 0.f;

    uint32_t aB[4], bB[4];
#pragma unroll
    for (int mt = 0; mt < 4; mt++)
        aB[mt] = abase + (uint32_t)(warp_m + mt * 16 + gid) * 128;
#pragma unroll
    for (int nt = 0; nt < 4; nt++)
        bB[nt] = abase + OFF_B + (uint32_t)(warp_n + nt * 8 + gid) * 128;
    uint32_t rx = (uint32_t)gid << 4;

    int nchunk = kl >> 6;
    for (int ch = 0; ch < nchunk; ch++) {
        int kc = ch << 6;
        if (ch) __syncthreads();

#pragma unroll
        for (int i = 0; i < 8; i++) {
            int flat = tid + (i << 8);
            int k = flat >> 5;
            int c4 = (flat & 31) << 2;
            float4 f = *(const float4*)(Ab + (long long)(kc + k) * M + m0 + c4);
            *(float4*)(stage + k * 132 + c4) = f;
        }
        __syncthreads();
        for (int k = p2k0; k < p2k0 + 32; k += 4) {
            float4 f = make_float4(stage[k * 132 + p2n],
                                   stage[(k + 1) * 132 + p2n],
                                   stage[(k + 2) * 132 + p2n],
                                   stage[(k + 3) * 132 + p2n]);
            uint2 hi, lo;
            split4(f, hi, lo);
            uint32_t sw = abase + sw128((uint32_t)p2n * 128 + k * 2);
            sts64(sw, hi);
            sts64(sw + 16384, lo);
        }
        __syncthreads();
#pragma unroll
        for (int i = 0; i < 8; i++) {
            int flat = tid + (i << 8);
            int k = flat >> 5;
            int c4 = (flat & 31) << 2;
            float4 f = *(const float4*)(Bb + (long long)(kc + k) * N + n0b + c4);
            *(float4*)(stage + k * 132 + c4) = f;
        }
        __syncthreads();
        for (int k = p2k0; k < p2k0 + 32; k += 4) {
            float4 f = make_float4(stage[k * 132 + p2n],
                                   stage[(k + 1) * 132 + p2n],
                                   stage[(k + 2) * 132 + p2n],
                                   stage[(k + 3) * 132 + p2n]);
            uint2 hi, lo;
            split4(f, hi, lo);
            uint32_t sw = abase + OFF_B + sw128((uint32_t)p2n * 128 + k * 2);
            sts64(sw, hi);
            sts64(sw + 16384, lo);
        }
        __syncthreads();

#pragma unroll
        for (int ks = 0; ks < 4; ks++) {
            uint32_t q0 = ((uint32_t)(ks * 32) + (uint32_t)tig * 4) ^ rx;
            uint32_t q1 = q0 ^ 16;
            uint32_t ah[4][4], al[4][4];
#pragma unroll
            for (int mt = 0; mt < 4; mt++) {
                uint32_t base = aB[mt];
                ah[mt][0] = lds32(base + q0);
                ah[mt][1] = lds32(base + 1024 + q0);
                ah[mt][2] = lds32(base + q1);
                ah[mt][3] = lds32(base + 1024 + q1);
                al[mt][0] = lds32lo(base + q0);
                al[mt][1] = lds32lo(base + 1024 + q0);
                al[mt][2] = lds32lo(base + q1);
                al[mt][3] = lds32lo(base + 1024 + q1);
            }
#pragma unroll
            for (int nt = 0; nt < 4; nt++) {
                uint32_t bb = bB[nt];
                uint32_t bh0 = lds32(bb + q0);
                uint32_t bh1 = lds32(bb + q1);
                uint32_t bl0 = lds32lo(bb + q0);
                uint32_t bl1 = lds32lo(bb + q1);
#pragma unroll
                for (int mt = 0; mt < 4; mt++) {
                    MMA16816(acc[mt][nt], ah[mt][0], ah[mt][1], ah[mt][2], ah[mt][3], bh0, bh1);
                    MMA16816(acc[mt][nt], ah[mt][0], ah[mt][1], ah[mt][2], ah[mt][3], bl0, bl1);
                    MMA16816(acc[mt][nt], al[mt][0], al[mt][1], al[mt][2], al[mt][3], bh0, bh1);
                }
            }
        }
    }

#pragma unroll
    for (int mt = 0; mt < 4; mt++) {
        long long r0 = m0 + warp_m + mt * 16 + gid;
#pragma unroll
        for (int nt = 0; nt < 4; nt++) {
            int cc = warp_n + nt * 8 + 2 * tig;
            float2 v0 = make_float2(acc[mt][nt][0], acc[mt][nt][1]);
            float2 v1 = make_float2(acc[mt][nt][2], acc[mt][nt][3]);
            *(float2*)&Cb[r0 * N + n0b + cc]       = v0;
            *(float2*)&Cb[(r0 + 8) * N + n0b + cc] = v1;
        }
    }
}

// ============================================================================
// Split-K TN GEMM partials (fp32): Cp[z] = A_slice^T @ B_slice
// ============================================================================
__global__ __launch_bounds__(256)
void gemm_tn_sk(const float* __restrict__ A, long long aO,
                const float* __restrict__ B, long long bO,
                float* __restrict__ Cp, int M, int N, int Ktot)
{
    int z = blockIdx.z;
    int g = z >> 3, c = z & 7;
    int kl = Ktot >> 3;
    const float* Ab = A + (long long)g * aO + (long long)c * kl * M;
    const float* Bb = B + (long long)g * bO + (long long)c * kl * N;
    float*       Cb = Cp + (long long)z * M * N;

    __shared__ __align__(16) float As[16][64];
    __shared__ __align__(16) float Bs[16][64];

    int tid = threadIdx.x;
    int m0 = blockIdx.y * 64;
    int n0 = blockIdx.x * 64;

    int lrow = tid >> 4;
    int lcol = (tid & 15) * 4;
    int tx = tid & 15;
    int ty = tid >> 4;

    const float* Ap = Ab + (long long)lrow * M + m0 + lcol;
    const float* Bp = Bb + (long long)lrow * N + n0 + lcol;

    float acc[4][4];
#pragma unroll
    for (int i = 0; i < 4; i++)
#pragma unroll
        for (int j = 0; j < 4; j++) acc[i][j] = 0.f;

    for (int k0 = 0; k0 < kl; k0 += 16) {
        *(float4*)&As[lrow][lcol] = *(const float4*)(Ap + (long long)k0 * M);
        *(float4*)&Bs[lrow][lcol] = *(const float4*)(Bp + (long long)k0 * N);
        __syncthreads();
#pragma unroll
        for (int kk = 0; kk < 16; kk++) {
            float4 a = *(const float4*)&As[kk][ty * 4];
            float4 bb4 = *(const float4*)&Bs[kk][tx * 4];
            float a4[4] = {a.x, a.y, a.z, a.w};
            float b4[4] = {bb4.x, bb4.y, bb4.z, bb4.w};
#pragma unroll
            for (int i = 0; i < 4; i++)
#pragma unroll
                for (int j = 0; j < 4; j++)
                    acc[i][j] = fmaf(a4[i], b4[j], acc[i][j]);
        }
        __syncthreads();
    }

#pragma unroll
    for (int i = 0; i < 4; i++) {
        int row = m0 + ty * 4 + i;
        float4 v = {acc[i][0], acc[i][1], acc[i][2], acc[i][3]};
        *(float4*)&Cb[(long long)row * N + n0 + tx * 4] = v;
    }
}

__global__ void reduce8(const float* __restrict__ Cp, float* __restrict__ C,
                        float alpha, int MN)
{
    int i = blockIdx.x * 256 + threadIdx.x;
    int g = blockIdx.y;
    const float* p = Cp + (long long)g * 8 * MN + i;
    float s = 0.f;
#pragma unroll
    for (int c = 0; c < 8; c++) s += p[(long long)c * MN];
    C[(long long)g * MN + i] = alpha * s;
}

__global__ void reduceS(const float* __restrict__ Cp, float* __restrict__ S,
                        const float* __restrict__ u, const float* __restrict__ bk,
                        const float* __restrict__ w, const float* __restrict__ bv,
                        float alpha, int MN, int M, int N)
{
    int i = blockIdx.x * 256 + threadIdx.x;
    int g = blockIdx.y;
    const float* p = Cp + (long long)g * 8 * MN + i;
    float ssum = 0.f;
#pragma unroll
    for (int c = 0; c < 8; c++) ssum += p[(long long)c * MN];
    int row = i / N, col = i - row * N;
    float uk = u[g * M + row], bki = bk[g * M + row];
    float wv = w[g * N + col], bvj = bv[g * N + col];
    ssum += uk * bvj + bki * wv + (float)NTOK * bki * bvj;
    S[(long long)g * MN + i] = alpha * ssum;
}

__global__ void colsum(const float* __restrict__ x, float* __restrict__ s)
{
    int c = blockIdx.x * 256 + threadIdx.x;
    float a0 = 0.f, a1 = 0.f, a2 = 0.f, a3 = 0.f;
    const float* p = x + c;
    for (int n = 0; n < NTOK; n += 4) {
        a0 += p[(long long)n * DDIM];
        a1 += p[(long long)(n + 1) * DDIM];
        a2 += p[(long long)(n + 2) * DDIM];
        a3 += p[(long long)(n + 3) * DDIM];
    }
    s[c] = (a0 + a1) + (a2 + a3);
}

// ============================================================================
// Batched vec @ mat: 8-way K-split x 32 cols per block; dual-set.
// ============================================================================
__global__ __launch_bounds__(256)
void vecmat3(const float* __restrict__ vec, long long vecStride,
             const float* __restrict__ mat, long long matO, long long matI, int bshift,
             const float* __restrict__ add, long long addStride,
             float* __restrict__ out, long long outStride,
             const float* __restrict__ vec2, const float* __restrict__ mat2,
             const float* __restrict__ add2, float* __restrict__ out2,
             int ysplit, int K, int N)
{
    int b = blockIdx.y;
    const float* vecu = vec; const float* matu = mat;
    const float* addu = add; float* outu = out;
    if (b >= ysplit) { b -= ysplit; vecu = vec2; matu = mat2; addu = add2; outu = out2; }
    int c = (threadIdx.x & 31) + blockIdx.x * 32;
    int s = threadIdx.x >> 5;
    const float* v = vecu + (long long)b * vecStride;
    const float* m = matu + (long long)(b >> bshift) * matO
                          + (long long)(b & ((1 << bshift) - 1)) * matI;
    int kpart = K >> 3;
    int kb = s * kpart;
    float a0 = 0.f, a1 = 0.f, a2 = 0.f, a3 = 0.f;
    if (c < N) {
        const float* mp = m + (long long)kb * N + c;
        const float* vp = v + kb;
        for (int k = 0; k < kpart; k += 4) {
            a0 = fmaf(vp[k],     mp[(long long)k * N], a0);
            a1 = fmaf(vp[k + 1], mp[(long long)(k + 1) * N], a1);
            a2 = fmaf(vp[k + 2], mp[(long long)(k + 2) * N], a2);
            a3 = fmaf(vp[k + 3], mp[(long long)(k + 3) * N], a3);
        }
    }
    __shared__ float red[256];
    red[threadIdx.x] = (a0 + a1) + (a2 + a3);
    __syncthreads();
    if (s == 0 && c < N) {
        float t = 0.f;
#pragma unroll
        for (int i = 0; i < 8; i++) t += red[threadIdx.x + i * 32];
        if (addu) t += addu[(long long)b * addStride + c];
        outu[(long long)b * outStride + c] = t;
    }
}

#define NOSET2 (const float*)nullptr, (const float*)nullptr, (float*)nullptr, (1<<30)
#define NOVEC2 nullptr, nullptr, nullptr, nullptr, (1<<30)

extern "C" void kernel_launch(void* const* d_in, const int* in_sizes, int n_in,
                              void* d_out, int out_size)
{
    (void)in_sizes; (void)n_in; (void)out_size;

    const float* x   = (const float*)d_in[0];
    const float* Wq1 = (const float*)d_in[1];
    const float* bq1 = (const float*)d_in[2];
    const float* Wk1 = (const float*)d_in[3];
    const float* bk1 = (const float*)d_in[4];
    const float* Wv1 = (const float*)d_in[5];
    const float* bv1 = (const float*)d_in[6];
    const float* Wo1 = (const float*)d_in[7];
    const float* bo1 = (const float*)d_in[8];
    const float* Wq2 = (const float*)d_in[9];
    const float* bq2 = (const float*)d_in[10];
    const float* Wk2 = (const float*)d_in[11];
    const float* bk2 = (const float*)d_in[12];
    const float* Wv2 = (const float*)d_in[13];
    const float* bv2 = (const float*)d_in[14];
    const float* Wo2 = (const float*)d_in[15];
    const float* bo2 = (const float*)d_in[16];
    const float* Wo  = (const float*)d_in[17];
    const float* bo  = (const float*)d_in[18];
    float* out = (float*)d_out;

    float *Gp, *G, *s, *u1, *w1, *S1, *T1, *P1, *bP1, *W1, *b1;
    float *Wo1k, *Wo1v, *bo1k, *bo1v, *Wo2e, *bo3;
    float *Wk2e, *Wv2e, *bk2e, *bv2e, *u2, *w2, *T2, *S2, *bP2, *P2;
    float *W23, *Wf, *b3, *bf;
    cudaGetSymbolAddress((void**)&Gp,   g_Gp);
    cudaGetSymbolAddress((void**)&G,    g_G);
    cudaGetSymbolAddress((void**)&s,    g_s);
    cudaGetSymbolAddress((void**)&u1,   g_u1);
    cudaGetSymbolAddress((void**)&w1,   g_w1);
    cudaGetSymbolAddress((void**)&S1,   g_S1);
    cudaGetSymbolAddress((void**)&T1,   g_T1);
    cudaGetSymbolAddress((void**)&P1,   g_P1);
    cudaGetSymbolAddress((void**)&bP1,  g_bP1);
    cudaGetSymbolAddress((void**)&W1,   g_W1);
    cudaGetSymbolAddress((void**)&b1,   g_b1);
    cudaGetSymbolAddress((void**)&Wo1k, g_Wo1k);
    cudaGetSymbolAddress((void**)&Wo1v, g_Wo1v);
    cudaGetSymbolAddress((void**)&bo1k, g_bo1k);
    cudaGetSymbolAddress((void**)&bo1v, g_bo1v);
    cudaGetSymbolAddress((void**)&Wo2e, g_Wo2e);
    cudaGetSymbolAddress((void**)&bo3,  g_bo3);
    cudaGetSymbolAddress((void**)&Wk2e, g_Wk2e);
    cudaGetSymbolAddress((void**)&Wv2e, g_Wv2e);
    cudaGetSymbolAddress((void**)&bk2e, g_bk2e);
    cudaGetSymbolAddress((void**)&bv2e, g_bv2e);
    cudaGetSymbolAddress((void**)&u2,   g_u2);
    cudaGetSymbolAddress((void**)&w2,   g_w2);
    cudaGetSymbolAddress((void**)&T2,   g_T2);
    cudaGetSymbolAddress((void**)&S2,   g_S2);
    cudaGetSymbolAddress((void**)&bP2,  g_bP2);
    cudaGetSymbolAddress((void**)&P2,   g_P2);
    cudaGetSymbolAddress((void**)&W23,  g_W23);
    cudaGetSymbolAddress((void**)&Wf,   g_Wf);
    cudaGetSymbolAddress((void**)&b3,   g_b3);
    cudaGetSymbolAddress((void**)&bf,   g_bf);

    cudaFuncSetAttribute(tgemm, cudaFuncAttributeMaxDynamicSharedMemorySize, TG_SMEM);
    cudaFuncSetAttribute(tgemm_tn, cudaFuncAttributeMaxDynamicSharedMemorySize, TG_SMEM);

    const float inv_sa1 = 0.08838834764831845f;  // 1/sqrt(128)
    const float inv_sa2 = 0.125f;                // 1/sqrt(64)

    cudaStream_t sd;
    cudaStreamCreateWithFlags(&sd, cudaStreamNonBlocking);
    cudaEvent_t e0, eA, eS1, eP1, eWW1, eB2, eS2, eW23, eD2;
    cudaEventCreateWithFlags(&e0,   cudaEventDisableTiming);
    cudaEventCreateWithFlags(&eA,   cudaEventDisableTiming);
    cudaEventCreateWithFlags(&eS1,  cudaEventDisableTiming);
    cudaEventCreateWithFlags(&eP1,  cudaEventDisableTiming);
    cudaEventCreateWithFlags(&eWW1, cudaEventDisableTiming);
    cudaEventCreateWithFlags(&eB2,  cudaEventDisableTiming);
    cudaEventCreateWithFlags(&eS2,  cudaEventDisableTiming);
    cudaEventCreateWithFlags(&eW23, cudaEventDisableTiming);
    cudaEventCreateWithFlags(&eD2,  cudaEventDisableTiming);

    // ---- fork ----
    cudaEventRecord(e0, 0);
    cudaStreamWaitEvent(sd, e0, 0);

    // SIDE block 1: input-only precomputes
    colsum<<<dim3(2), 256, 0, sd>>>(x, s);
    vecmat3<<<dim3(4, 16), 256, 0, sd>>>(s, 0, Wk1, (long long)DDIM*AD1, 0, 0,
                                         (const float*)nullptr, 0, u1, AD1,
                                         s, Wv1, nullptr, w1, 8, DDIM, AD1);
    cudaEventRecord(eA, sd);
    tgemm<<<dim3(1, 8, 16), 256, TG_SMEM, sd>>>(Wo1, (long long)NQH*AD1*DDIM, 0,
        Wk2, (const float*)nullptr, Wo1k,
        Wv2, (const float*)nullptr, Wo1v, 8,
        (long long)DDIM*AD2, 0, 0,
        (long long)NQH*AD1*AD2, 0, AD2, AD2, DDIM, 64, 0);
    vecmat3<<<dim3(2, 16), 256, 0, sd>>>(bo1, DDIM, Wk2, (long long)DDIM*AD2, 0, 0,
                                         bk2, AD2, bo1k, AD2,
                                         bo1, Wv2, bv2, bo1v, 8, DDIM, AD2);
    tgemm<<<dim3(4, 4, 8), 256, TG_SMEM, sd>>>(Wo2, (long long)NQH*AD2*DDIM, 0,
        Wo, (const float*)nullptr, Wo2e, NOSET2,
        0, 0, 0,
        (long long)DDIM*DDIM, 0, DDIM, DDIM, NQH*AD2, 128, 0);
    vecmat3<<<dim3(16, 8), 256, 0, sd>>>(bo2, DDIM, Wo, 0, 0, 0,
                                         bo, 0, bo3, DDIM, NOVEC2, DDIM, DDIM);

    // MAIN block 1: G = x^T x (tensor-core split-K), T1, S1
    tgemm_tn<<<dim3(4, 4, 8), 256, TG_SMEM>>>(x, 0, x, 0, Gp, DDIM, DDIM, NTOK);
    reduce8<<<dim3(1024, 1), 256>>>(Gp, G, 1.f, DDIM*DDIM);
    tgemm<<<dim3(1, 4, 8), 256, TG_SMEM>>>(G, 0, 0,
        Wv1, (const float*)nullptr, T1, NOSET2,
        (long long)DDIM*AD1, 0, 0,
        (long long)DDIM*AD1, 0, AD1, AD1, DDIM, 128, 0);
    gemm_tn_sk<<<dim3(2, 2, 64), 256>>>(Wk1, (long long)DDIM*AD1,
                                        T1, (long long)DDIM*AD1,
                                        Gp, AD1, AD1, DDIM);
    cudaStreamWaitEvent(0, eA, 0);
    reduceS<<<dim3(64, 8), 256>>>(Gp, S1, u1, bk1, w1, bv1,
                                  inv_sa1, AD1*AD1, AD1, AD1);
    cudaEventRecord(eS1, 0);

    // SIDE block 2: bP1; b1; bk2e/bv2e = bP1@Wo1k/v + bo1k/v
    cudaStreamWaitEvent(sd, eS1, 0);
    vecmat3<<<dim3(4, 64), 256, 0, sd>>>(bq1, AD1, S1, (long long)AD1*AD1, 0, 3,
                                         (const float*)nullptr, 0, bP1, AD1,
                                         NOVEC2, AD1, AD1);
    vecmat3<<<dim3(16, 8), 256, 0, sd>>>(bP1, NQH*AD1, Wo1, (long long)NQH*AD1*DDIM, 0, 0,
                                         bo1, DDIM, b1, DDIM, NOVEC2, NQH*AD1, DDIM);
    vecmat3<<<dim3(2, 16), 256, 0, sd>>>(bP1, NQH*AD1, Wo1k, (long long)NQH*AD1*AD2, 0, 0,
                                         bo1k, AD2, bk2e, AD2,
                                         bP1, Wo1v, bo1v, bv2e, 8, NQH*AD1, AD2);
    cudaEventRecord(eB2, sd);

    // MAIN block 2: P1; Wk2e/Wv2e; u2w2 (main); T2; S2 partials
    tgemm<<<dim3(1, 4, 64), 256, TG_SMEM>>>(Wq1, (long long)NQH*DDIM*AD1, (long long)DDIM*AD1,
        S1, (const float*)nullptr, P1, NOSET2,
        (long long)AD1*AD1, 0, 0,
        (long long)DDIM*NQH*AD1, AD1, NQH*AD1, AD1, AD1, 128, 3);
    cudaEventRecord(eP1, 0);
    tgemm<<<dim3(1, 4, 16), 256, TG_SMEM>>>(P1, (long long)DDIM*NQH*AD1, 0,
        Wo1k, (const float*)nullptr, Wk2e,
        Wo1v, (const float*)nullptr, Wv2e, 8,
        (long long)NQH*AD1*AD2, 0, 0,
        (long long)DDIM*AD2, 0, AD2, AD2, NQH*AD1, 64, 0);
    vecmat3<<<dim3(2, 16), 256>>>(s, 0, Wk2e, (long long)DDIM*AD2, 0, 0,
                                  (const float*)nullptr, 0, u2, AD2,
                                  s, Wv2e, nullptr, w2, 8, DDIM, AD2);
    tgemm<<<dim3(1, 4, 8), 256, TG_SMEM>>>(G, 0, 0,
        Wv2e, (const float*)nullptr, T2, NOSET2,
        (long long)DDIM*AD2, 0, 0,
        (long long)DDIM*AD2, 0, AD2, AD2, DDIM, 64, 0);
    gemm_tn_sk<<<dim3(1, 1, 64), 256>>>(Wk2e, (long long)DDIM*AD2,
                                        T2, (long long)DDIM*AD2,
                                        Gp, AD2, AD2, DDIM);
    cudaStreamWaitEvent(0, eB2, 0);
    reduceS<<<dim3(16, 8), 256>>>(Gp, S2, u2, bk2e, w2, bv2e,
                                  inv_sa2, AD2*AD2, AD2, AD2);
    cudaEventRecord(eS2, 0);

    // SIDE block 3: W1 = P1cat @ Wo1 (shadow of main block 2)
    cudaStreamWaitEvent(sd, eP1, 0);
    tgemm<<<dim3(4, 4, 8), 256, TG_SMEM, sd>>>(P1, (long long)DDIM*NQH*AD1, 0,
        Wo1, (const float*)nullptr, W1, NOSET2,
        (long long)NQH*AD1*DDIM, 0, 0,
        (long long)DDIM*DDIM, 0, DDIM, DDIM, NQH*AD1, 128, 0);
    cudaEventRecord(eWW1, sd);

    // MAIN block 3: P2; W23 = P2cat@Wo2e; Wf = W1@W23
    tgemm<<<dim3(1, 4, 64), 256, TG_SMEM>>>(Wq2, (long long)NQH*DDIM*AD2, (long long)DDIM*AD2,
        S2, (const float*)nullptr, P2, NOSET2,
        (long long)AD2*AD2, 0, 0,
        (long long)DDIM*NQH*AD2, AD2, NQH*AD2, AD2, AD2, 64, 3);
    tgemm<<<dim3(4, 4, 8), 256, TG_SMEM>>>(P2, (long long)DDIM*NQH*AD2, 0,
        Wo2e, (const float*)nullptr, W23, NOSET2,
        (long long)DDIM*DDIM, 0, 0,
        (long long)DDIM*DDIM, 0, DDIM, DDIM, NQH*AD2, 128, 0);
    cudaEventRecord(eW23, 0);
    cudaStreamWaitEvent(0, eWW1, 0);
    tgemm<<<dim3(4, 4, 8), 256, TG_SMEM>>>(W1, (long long)DDIM*DDIM, 0,
        W23, (const float*)nullptr, Wf, NOSET2,
        (long long)DDIM*DDIM, 0, 0,
        (long long)DDIM*DDIM, 0, DDIM, DDIM, DDIM, 128, 0);

    // SIDE block 4: bP2; b3 = bP2@Wo2e + bo3; bf = b1@W23 + b3
    cudaStreamWaitEvent(sd, eS2, 0);
    vecmat3<<<dim3(2, 64), 256, 0, sd>>>(bq2, AD2, S2, (long long)AD2*AD2, 0, 3,
                                         (const float*)nullptr, 0, bP2, AD2,
                                         NOVEC2, AD2, AD2);
    vecmat3<<<dim3(16, 8), 256, 0, sd>>>(bP2, NQH*AD2, Wo2e, (long long)DDIM*DDIM, 0, 0,
                                         bo3, DDIM, b3, DDIM, NOVEC2, NQH*AD2, DDIM);
    cudaStreamWaitEvent(sd, eW23, 0);
    vecmat3<<<dim3(16, 8), 256, 0, sd>>>(b1, DDIM, W23, (long long)DDIM*DDIM, 0, 0,
                                         b3, DDIM, bf, DDIM, NOVEC2, DDIM, DDIM);
    cudaEventRecord(eD2, sd);

    // MAIN: join; out = x @ Wf + bf
    cudaStreamWaitEvent(0, eD2, 0);
    tgemm<<<dim3(4, 16, 8), 256, TG_SMEM>>>(x, 0, 0,
        Wf, bf, out, NOSET2,
        (long long)DDIM*DDIM, 0, DDIM,
        (long long)NTOK*DDIM, 0, DDIM, DDIM, DDIM, 128, 0);
}